// round 5
// baseline (speedup 1.0000x reference)
#include <cuda_runtime.h>
#include <cuda_bf16.h>
#include <math.h>
#include <stdint.h>

#define B_    4
#define N_    4096
#define DIN_  512
#define DOUT_ 128
#define MAXDEG 256
#define NEG_BIG -1e30f

// ---------------- scratch (static device memory; no allocs) ----------------
__device__ float g_wh[B_ * N_ * DOUT_];     // x @ W            (8 MB)
__device__ float g_out[B_ * N_ * DOUT_];    // att @ wh         (8 MB)
__device__ float g_s[B_ * N_];              // wh @ a_src
__device__ float g_d[B_ * N_];              // wh @ a_dst
__device__ float g_sumwh[B_ * DOUT_];       // per-graph colsum (deg==0 fallback)
__device__ int   g_cols[N_ * MAXDEG];
__device__ int   g_deg[N_];
__device__ uint32_t g_Whi[DIN_ * DOUT_ / 2];  // W split hi (bf16x2 packed)
__device__ uint32_t g_Wlo[DIN_ * DOUT_ / 2];  // W split lo

// ============================ helpers =======================================
__device__ __forceinline__ uint32_t smem_u32(const void* p) {
    uint32_t a;
    asm("{ .reg .u64 t; cvta.to.shared.u64 t, %1; cvt.u32.u64 %0, t; }" : "=r"(a) : "l"(p));
    return a;
}
__device__ __forceinline__ void ldm_x4(uint32_t* f, uint32_t addr) {
    asm volatile("ldmatrix.sync.aligned.m8n8.x4.shared.b16 {%0,%1,%2,%3}, [%4];"
                 : "=r"(f[0]), "=r"(f[1]), "=r"(f[2]), "=r"(f[3]) : "r"(addr));
}
__device__ __forceinline__ void ldm_x4t(uint32_t* f, uint32_t addr) {
    asm volatile("ldmatrix.sync.aligned.m8n8.x4.trans.shared.b16 {%0,%1,%2,%3}, [%4];"
                 : "=r"(f[0]), "=r"(f[1]), "=r"(f[2]), "=r"(f[3]) : "r"(addr));
}
__device__ __forceinline__ void mma_bf16(float* c, const uint32_t* a, const uint32_t* b) {
    asm volatile(
        "mma.sync.aligned.m16n8k16.row.col.f32.bf16.bf16.f32 "
        "{%0,%1,%2,%3}, {%4,%5,%6,%7}, {%8,%9}, {%0,%1,%2,%3};"
        : "+f"(c[0]), "+f"(c[1]), "+f"(c[2]), "+f"(c[3])
        : "r"(a[0]), "r"(a[1]), "r"(a[2]), "r"(a[3]), "r"(b[0]), "r"(b[1]));
}
__device__ __forceinline__ uint32_t pack_bf16(float x, float y) {
    __nv_bfloat16 hx = __float2bfloat16_rn(x);
    __nv_bfloat16 hy = __float2bfloat16_rn(y);
    return ((uint32_t)__bfloat16_as_ushort(hy) << 16) | __bfloat16_as_ushort(hx);
}
__device__ __forceinline__ float bf_res(float f) {
    return f - __bfloat162float(__float2bfloat16_rn(f));
}

// =============== W split (hi/lo bf16) + zero g_sumwh =======================
__global__ __launch_bounds__(256) void convw_kernel(const float* __restrict__ W) {
    if (blockIdx.x < 2) g_sumwh[blockIdx.x * 256 + threadIdx.x] = 0.0f;
    int i = blockIdx.x * 256 + threadIdx.x;      // one float4 each, 16384 total
    float4 v = ((const float4*)W)[i];
    g_Whi[i * 2]     = pack_bf16(v.x, v.y);
    g_Whi[i * 2 + 1] = pack_bf16(v.z, v.w);
    g_Wlo[i * 2]     = pack_bf16(bf_res(v.x), bf_res(v.y));
    g_Wlo[i * 2 + 1] = pack_bf16(bf_res(v.z), bf_res(v.w));
}

// =============== CSR build: warp/row, 4 loads in flight ====================
__global__ void csr_build_kernel(const float* __restrict__ adj) {
    int warp = (blockIdx.x * blockDim.x + threadIdx.x) >> 5;
    int lane = threadIdx.x & 31;
    if (warp >= N_) return;
    const float4* row = (const float4*)(adj + (size_t)warp * N_);
    int cnt = 0;
    for (int base = 0; base < N_; base += 512) {
        float4 v0 = row[(base >> 2) + lane];
        float4 v1 = row[(base >> 2) + 32 + lane];
        float4 v2 = row[(base >> 2) + 64 + lane];
        float4 v3 = row[(base >> 2) + 96 + lane];
        float c16[16] = {v0.x, v0.y, v0.z, v0.w, v1.x, v1.y, v1.z, v1.w,
                         v2.x, v2.y, v2.z, v2.w, v3.x, v3.y, v3.z, v3.w};
#pragma unroll
        for (int h = 0; h < 4; h++) {
#pragma unroll
            for (int c = 0; c < 4; c++) {
                float f = c16[h * 4 + c];
                unsigned m = __ballot_sync(0xffffffffu, f > 0.0f);
                if (f > 0.0f) {
                    int pos = cnt + __popc(m & ((1u << lane) - 1u));
                    if (pos < MAXDEG)
                        g_cols[warp * MAXDEG + pos] = base + h * 128 + lane * 4 + c;
                }
                cnt += __popc(m);
            }
        }
    }
    if (lane == 0) g_deg[warp] = cnt < MAXDEG ? cnt : MAXDEG;
}

// ============ HMMA GEMM: wh = x @ W  (M=16384, N=128, K=512) ===============
#define KC 32
#define NCH (DIN_ / KC)          // 16 chunks
#define A_STG 16384              // 128 rows * 128B
#define B_STG 16384              // hi 8KB + lo 8KB
#define SM_A 0
#define SM_B (2 * A_STG)
#define SM_SD (SM_B + 2 * B_STG)          // s_sm[128], d_sm[128]
#define SM_AV (SM_SD + 1024)              // a_s[128], a_d[128]
#define SM_CS (SM_AV + 1024)              // cs[128] column sums
#define SMEM_TOTAL (SM_CS + 512)

__device__ __forceinline__ uint32_t a_off(int r, int gran) {
    return (uint32_t)(r * 128 + ((gran ^ (r & 7)) << 4));
}
__device__ __forceinline__ uint32_t b_off2(int k, int gran) {
    return (uint32_t)(k * 256 + ((gran ^ (k & 7)) << 4));
}

__global__ __launch_bounds__(256, 1) void gemm_hmma_kernel(
    const float* __restrict__ x, const float* __restrict__ a) {
    extern __shared__ char smem[];
    const uint32_t sb = smem_u32(smem);
    const int tid = threadIdx.x;
    const int wid = tid >> 5, lane = tid & 31;
    const int wm = wid >> 1, wn = wid & 1;
    const int tig = lane & 3, grp = lane >> 2;

    float* s_sm = (float*)(smem + SM_SD);
    float* d_sm = (float*)(smem + SM_SD + 512);
    float* a_s  = (float*)(smem + SM_AV);
    float* a_d  = (float*)(smem + SM_AV + 512);
    float* cs   = (float*)(smem + SM_CS);
    if (tid < 128) {
        s_sm[tid] = 0.0f; d_sm[tid] = 0.0f; cs[tid] = 0.0f;
        a_s[tid] = a[tid]; a_d[tid] = a[DOUT_ + tid];
    }

    const int R0 = blockIdx.x * 128;
    const int arow = tid >> 1, akoff = (tid & 1) * 16;
    const float* pA = x + (size_t)(R0 + arow) * DIN_ + akoff;
    // B copy coords: thread -> (k, gr0/gr1), 16B granules
    const int bk = tid >> 3, bgr = (tid & 7) * 2;
    const uint4* Whi4 = (const uint4*)g_Whi;
    const uint4* Wlo4 = (const uint4*)g_Wlo;

    float acc[2][8][4];
#pragma unroll
    for (int i = 0; i < 2; i++)
#pragma unroll
        for (int j = 0; j < 8; j++)
#pragma unroll
            for (int q = 0; q < 4; q++) acc[i][j][q] = 0.0f;

    float4 ra[4];
    uint4 rbh[2], rbl[2];
    // prologue: chunk 0
#pragma unroll
    for (int i = 0; i < 4; i++) ra[i] = *(const float4*)(pA + i * 4);
    {
        int gi = bk * 16 + bgr;
        rbh[0] = Whi4[gi];     rbh[1] = Whi4[gi + 1];
        rbl[0] = Wlo4[gi];     rbl[1] = Wlo4[gi + 1];
    }

    for (int c = 0; c < NCH; c++) {
        const int buf = c & 1;
        char* Abuf = smem + SM_A + buf * A_STG;
        char* Bhi  = smem + SM_B + buf * B_STG;
        char* Blo  = Bhi + 8192;

        // store prefetched chunk c into smem
        {
            const float* fa = (const float*)ra;
#pragma unroll
            for (int p = 0; p < 8; p++) {
                float f0 = fa[2 * p], f1 = fa[2 * p + 1];
                uint32_t hv = pack_bf16(f0, f1);
                uint32_t lv = pack_bf16(bf_res(f0), bf_res(f1));
                int kl = akoff + 2 * p;
                int gr = kl >> 3, wi = (kl & 7) * 2;
                *(uint32_t*)(Abuf + a_off(arow, gr) + wi)     = hv;
                *(uint32_t*)(Abuf + a_off(arow, gr + 4) + wi) = lv;
            }
            *(uint4*)(Bhi + b_off2(bk, bgr))     = rbh[0];
            *(uint4*)(Bhi + b_off2(bk, bgr + 1)) = rbh[1];
            *(uint4*)(Blo + b_off2(bk, bgr))     = rbl[0];
            *(uint4*)(Blo + b_off2(bk, bgr + 1)) = rbl[1];
        }
        __syncthreads();

        // prefetch chunk c+1 into regs
        if (c + 1 < NCH) {
            const float* qA = pA + (c + 1) * KC;
#pragma unroll
            for (int i = 0; i < 4; i++) ra[i] = *(const float4*)(qA + i * 4);
            int gi = (c + 1) * 512 + bk * 16 + bgr;
            rbh[0] = Whi4[gi];     rbh[1] = Whi4[gi + 1];
            rbl[0] = Wlo4[gi];     rbl[1] = Wlo4[gi + 1];
        }

        // ---- MMA on chunk c ----
        const uint32_t Abase = sb + SM_A + buf * A_STG;
        const uint32_t BhiB  = sb + SM_B + buf * B_STG;
        const uint32_t BloB  = BhiB + 8192;
#pragma unroll
        for (int ks = 0; ks < 2; ks++) {
            uint32_t ahi[2][4], alo[2][4];
#pragma unroll
            for (int mt = 0; mt < 2; mt++) {
                int R = wm * 32 + mt * 16 + (lane & 15);
                int gh = 2 * ks + (lane >> 4);
                ldm_x4(ahi[mt], Abase + a_off(R, gh));
                ldm_x4(alo[mt], Abase + a_off(R, gh + 4));
            }
            int kk = 16 * ks + (lane & 15);
#pragma unroll
            for (int ntp = 0; ntp < 4; ntp++) {
                int gn = wn * 8 + ntp * 2 + (lane >> 4);
                uint32_t bhi[4], blo[4];
                ldm_x4t(bhi, BhiB + b_off2(kk, gn));
                ldm_x4t(blo, BloB + b_off2(kk, gn));
#pragma unroll
                for (int mt = 0; mt < 2; mt++) {
                    mma_bf16(acc[mt][ntp * 2],     ahi[mt], bhi);
                    mma_bf16(acc[mt][ntp * 2 + 1], ahi[mt], bhi + 2);
                    mma_bf16(acc[mt][ntp * 2],     ahi[mt], blo);
                    mma_bf16(acc[mt][ntp * 2 + 1], ahi[mt], blo + 2);
                    mma_bf16(acc[mt][ntp * 2],     alo[mt], bhi);
                    mma_bf16(acc[mt][ntp * 2 + 1], alo[mt], bhi + 2);
                }
            }
        }
        __syncthreads();
    }

    // ---- epilogue: store wh, fused s/d dots + column sums ----
    float sacc[2][2] = {{0, 0}, {0, 0}}, dacc[2][2] = {{0, 0}, {0, 0}};
#pragma unroll
    for (int mt = 0; mt < 2; mt++) {
        int rbase = R0 + wm * 32 + mt * 16 + grp;
#pragma unroll
        for (int nt = 0; nt < 8; nt++) {
            int col = wn * 64 + nt * 8 + tig * 2;
            float* cf = acc[mt][nt];
            sacc[mt][0] += cf[0] * a_s[col] + cf[1] * a_s[col + 1];
            sacc[mt][1] += cf[2] * a_s[col] + cf[3] * a_s[col + 1];
            dacc[mt][0] += cf[0] * a_d[col] + cf[1] * a_d[col + 1];
            dacc[mt][1] += cf[2] * a_d[col] + cf[3] * a_d[col + 1];
            *(float2*)&g_wh[(size_t)rbase * DOUT_ + col]       = make_float2(cf[0], cf[1]);
            *(float2*)&g_wh[(size_t)(rbase + 8) * DOUT_ + col] = make_float2(cf[2], cf[3]);

            float v0 = cf[0] + cf[2];
            float v1 = cf[1] + cf[3];
#pragma unroll
            for (int off = 16; off >= 4; off >>= 1) {
                v0 += __shfl_down_sync(0xffffffffu, v0, off);
                v1 += __shfl_down_sync(0xffffffffu, v1, off);
            }
            if (lane < 4) {
                atomicAdd(&cs[col], v0);
                atomicAdd(&cs[col + 1], v1);
            }
        }
    }
#pragma unroll
    for (int mt = 0; mt < 2; mt++)
#pragma unroll
        for (int h = 0; h < 2; h++) {
            sacc[mt][h] += __shfl_xor_sync(0xffffffffu, sacc[mt][h], 1);
            sacc[mt][h] += __shfl_xor_sync(0xffffffffu, sacc[mt][h], 2);
            dacc[mt][h] += __shfl_xor_sync(0xffffffffu, dacc[mt][h], 1);
            dacc[mt][h] += __shfl_xor_sync(0xffffffffu, dacc[mt][h], 2);
        }
    if (tig == 0) {
#pragma unroll
        for (int mt = 0; mt < 2; mt++) {
            int r = wm * 32 + mt * 16 + grp;
            atomicAdd(&s_sm[r], sacc[mt][0]);
            atomicAdd(&s_sm[r + 8], sacc[mt][1]);
            atomicAdd(&d_sm[r], dacc[mt][0]);
            atomicAdd(&d_sm[r + 8], dacc[mt][1]);
        }
    }
    __syncthreads();
    if (tid < 128) {
        g_s[R0 + tid] = s_sm[tid];
        g_d[R0 + tid] = d_sm[tid];
        int b = R0 / N_;
        atomicAdd(&g_sumwh[b * DOUT_ + tid], cs[tid]);
    }
}

// ---------------- attention SpMM (one graph per launch) ----------------
__global__ __launch_bounds__(256) void attn_kernel(int b) {
    __shared__ float sh_p[8][MAXDEG];
    __shared__ int   sh_j[8][MAXDEG];
    int i = blockIdx.x * 8 + (threadIdx.x >> 5);   // row within graph
    int lane = threadIdx.x & 31;
    int w = (threadIdx.x >> 5);
    if (i >= N_) return;
    int deg = g_deg[i];
    int gw = b * N_ + i;

    float4* outr = (float4*)&g_out[(size_t)gw * DOUT_];

    if (deg == 0) {
        const float4* sw = (const float4*)&g_sumwh[b * DOUT_];
        float4 m = sw[lane];
        float inv = 1.0f / (float)N_;
        outr[lane] = make_float4(m.x * inv, m.y * inv, m.z * inv, m.w * inv);
        return;
    }

    float si = g_s[gw];
    float mx = NEG_BIG;
    for (int t = lane; t < deg; t += 32) {
        int j = g_cols[i * MAXDEG + t];
        float e = si + g_d[(size_t)b * N_ + j];
        e = e > 0.0f ? e : 0.01f * e;
        sh_j[w][t] = j;
        sh_p[w][t] = e;
        mx = fmaxf(mx, e);
    }
#pragma unroll
    for (int off = 16; off > 0; off >>= 1)
        mx = fmaxf(mx, __shfl_xor_sync(0xffffffffu, mx, off));
    __syncwarp();

    float se = 0.0f;
    for (int t = lane; t < deg; t += 32) {
        float p = expf(sh_p[w][t] - mx);
        sh_p[w][t] = p;
        se += p;
    }
#pragma unroll
    for (int off = 16; off > 0; off >>= 1)
        se += __shfl_xor_sync(0xffffffffu, se, off);
    float inv = 1.0f / se;
    __syncwarp();

    const float4* whb = (const float4*)&g_wh[(size_t)b * N_ * DOUT_];
    float4 acc0 = make_float4(0.f, 0.f, 0.f, 0.f);
    float4 acc1 = make_float4(0.f, 0.f, 0.f, 0.f);
    float4 acc2 = make_float4(0.f, 0.f, 0.f, 0.f);
    float4 acc3 = make_float4(0.f, 0.f, 0.f, 0.f);
    int k = 0;
    for (; k + 4 <= deg; k += 4) {
        float p0 = sh_p[w][k] * inv,     p1 = sh_p[w][k + 1] * inv;
        float p2 = sh_p[w][k + 2] * inv, p3 = sh_p[w][k + 3] * inv;
        int j0 = sh_j[w][k],     j1 = sh_j[w][k + 1];
        int j2 = sh_j[w][k + 2], j3 = sh_j[w][k + 3];
        float4 v0 = whb[(size_t)j0 * 32 + lane];
        float4 v1 = whb[(size_t)j1 * 32 + lane];
        float4 v2 = whb[(size_t)j2 * 32 + lane];
        float4 v3 = whb[(size_t)j3 * 32 + lane];
        acc0.x += p0 * v0.x; acc0.y += p0 * v0.y; acc0.z += p0 * v0.z; acc0.w += p0 * v0.w;
        acc1.x += p1 * v1.x; acc1.y += p1 * v1.y; acc1.z += p1 * v1.z; acc1.w += p1 * v1.w;
        acc2.x += p2 * v2.x; acc2.y += p2 * v2.y; acc2.z += p2 * v2.z; acc2.w += p2 * v2.w;
        acc3.x += p3 * v3.x; acc3.y += p3 * v3.y; acc3.z += p3 * v3.z; acc3.w += p3 * v3.w;
    }
    for (; k < deg; k++) {
        float p0 = sh_p[w][k] * inv;
        float4 v0 = whb[(size_t)sh_j[w][k] * 32 + lane];
        acc0.x += p0 * v0.x; acc0.y += p0 * v0.y; acc0.z += p0 * v0.z; acc0.w += p0 * v0.w;
    }
    outr[lane] = make_float4(acc0.x + acc1.x + acc2.x + acc3.x,
                             acc0.y + acc1.y + acc2.y + acc3.y,
                             acc0.z + acc1.z + acc2.z + acc3.z,
                             acc0.w + acc1.w + acc2.w + acc3.w);
}

// ---------------- final: y = relu(adj @ out) (one graph per launch) --------
__global__ __launch_bounds__(256) void final_kernel(float* __restrict__ y, int b) {
    int i = blockIdx.x * 8 + (threadIdx.x >> 5);
    int lane = threadIdx.x & 31;
    if (i >= N_) return;
    int deg = g_deg[i];
    int gw = b * N_ + i;

    const float4* outb = (const float4*)&g_out[(size_t)b * N_ * DOUT_];
    float4 acc0 = make_float4(0.f, 0.f, 0.f, 0.f);
    float4 acc1 = make_float4(0.f, 0.f, 0.f, 0.f);
    float4 acc2 = make_float4(0.f, 0.f, 0.f, 0.f);
    float4 acc3 = make_float4(0.f, 0.f, 0.f, 0.f);
    int k = 0;
    for (; k + 4 <= deg; k += 4) {
        int j0 = g_cols[i * MAXDEG + k],     j1 = g_cols[i * MAXDEG + k + 1];
        int j2 = g_cols[i * MAXDEG + k + 2], j3 = g_cols[i * MAXDEG + k + 3];
        float4 v0 = outb[(size_t)j0 * 32 + lane];
        float4 v1 = outb[(size_t)j1 * 32 + lane];
        float4 v2 = outb[(size_t)j2 * 32 + lane];
        float4 v3 = outb[(size_t)j3 * 32 + lane];
        acc0.x += v0.x; acc0.y += v0.y; acc0.z += v0.z; acc0.w += v0.w;
        acc1.x += v1.x; acc1.y += v1.y; acc1.z += v1.z; acc1.w += v1.w;
        acc2.x += v2.x; acc2.y += v2.y; acc2.z += v2.z; acc2.w += v2.w;
        acc3.x += v3.x; acc3.y += v3.y; acc3.z += v3.z; acc3.w += v3.w;
    }
    for (; k < deg; k++) {
        float4 v0 = outb[(size_t)g_cols[i * MAXDEG + k] * 32 + lane];
        acc0.x += v0.x; acc0.y += v0.y; acc0.z += v0.z; acc0.w += v0.w;
    }
    float4 r = make_float4(fmaxf(acc0.x + acc1.x + acc2.x + acc3.x, 0.f),
                           fmaxf(acc0.y + acc1.y + acc2.y + acc3.y, 0.f),
                           fmaxf(acc0.z + acc1.z + acc2.z + acc3.z, 0.f),
                           fmaxf(acc0.w + acc1.w + acc2.w + acc3.w, 0.f));
    ((float4*)&y[(size_t)gw * DOUT_])[lane] = r;
}

// ---------------- launch ----------------
extern "C" void kernel_launch(void* const* d_in, const int* in_sizes, int n_in,
                              void* d_out, int out_size) {
    const float* x   = (const float*)d_in[0];  // (B, N, DIN)
    const float* adj = (const float*)d_in[1];  // (N, N)
    const float* wts = (const float*)d_in[2];  // (DIN, DOUT)
    const float* a   = (const float*)d_in[3];  // (2*DOUT, 1)
    float* y = (float*)d_out;

    static cudaStream_t s2;
    static cudaEvent_t evA, evW, evC, evB[B_], evF;
    static int inited = 0;
    if (!inited) {
        cudaFuncSetAttribute(gemm_hmma_kernel,
                             cudaFuncAttributeMaxDynamicSharedMemorySize, SMEM_TOTAL);
        cudaStreamCreateWithFlags(&s2, cudaStreamNonBlocking);
        cudaEventCreateWithFlags(&evA, cudaEventDisableTiming);
        cudaEventCreateWithFlags(&evW, cudaEventDisableTiming);
        cudaEventCreateWithFlags(&evC, cudaEventDisableTiming);
        for (int b = 0; b < B_; b++)
            cudaEventCreateWithFlags(&evB[b], cudaEventDisableTiming);
        cudaEventCreateWithFlags(&evF, cudaEventDisableTiming);
        inited = 1;
    }

    cudaStream_t s0 = 0;

    // fork: s2 runs convW then csr, s0 runs the GEMM (needs convW only)
    cudaEventRecord(evA, s0);
    cudaStreamWaitEvent(s2, evA, 0);
    convw_kernel<<<DIN_ * DOUT_ / 1024, 256, 0, s2>>>(wts);
    cudaEventRecord(evW, s2);
    csr_build_kernel<<<N_ / 8, 256, 0, s2>>>(adj);
    cudaEventRecord(evC, s2);

    cudaStreamWaitEvent(s0, evW, 0);
    gemm_hmma_kernel<<<(B_ * N_) / 128, 256, SMEM_TOTAL, s0>>>(x, a);
    cudaStreamWaitEvent(s0, evC, 0);

    // pipelined per-graph attn (s0) -> final (s2)
    for (int b = 0; b < B_; b++) {
        attn_kernel<<<N_ / 8, 256, 0, s0>>>(b);
        cudaEventRecord(evB[b], s0);
        cudaStreamWaitEvent(s2, evB[b], 0);
        final_kernel<<<N_ / 8, 256, 0, s2>>>(y, b);
    }
    cudaEventRecord(evF, s2);
    cudaStreamWaitEvent(s0, evF, 0);
}

// round 6
// speedup vs baseline: 1.1340x; 1.1340x over previous
#include <cuda_runtime.h>
#include <cuda_bf16.h>
#include <math.h>
#include <stdint.h>

#define B_    4
#define N_    4096
#define DIN_  512
#define DOUT_ 128
#define MAXDEG 256
#define NEG_BIG -1e30f

// ---------------- scratch (static device memory; no allocs) ----------------
__device__ float g_wh[B_ * N_ * DOUT_];     // x @ W            (8 MB)
__device__ float g_out[B_ * N_ * DOUT_];    // att @ wh         (8 MB)
__device__ float g_s[B_ * N_];              // wh @ a_src
__device__ float g_d[B_ * N_];              // wh @ a_dst
__device__ float g_sumwh[B_ * DOUT_];       // per-graph colsum (deg==0 fallback)
__device__ int   g_cols[N_ * MAXDEG];
__device__ int   g_deg[N_];
__device__ uint32_t g_Whi[DIN_ * DOUT_ / 2];  // W split hi (bf16x2 packed)
__device__ uint32_t g_Wlo[DIN_ * DOUT_ / 2];  // W split lo

// ============================ helpers =======================================
__device__ __forceinline__ uint32_t smem_u32(const void* p) {
    uint32_t a;
    asm("{ .reg .u64 t; cvta.to.shared.u64 t, %1; cvt.u32.u64 %0, t; }" : "=r"(a) : "l"(p));
    return a;
}
__device__ __forceinline__ void ldm_x4(uint32_t* f, uint32_t addr) {
    asm volatile("ldmatrix.sync.aligned.m8n8.x4.shared.b16 {%0,%1,%2,%3}, [%4];"
                 : "=r"(f[0]), "=r"(f[1]), "=r"(f[2]), "=r"(f[3]) : "r"(addr));
}
__device__ __forceinline__ void ldm_x4t(uint32_t* f, uint32_t addr) {
    asm volatile("ldmatrix.sync.aligned.m8n8.x4.trans.shared.b16 {%0,%1,%2,%3}, [%4];"
                 : "=r"(f[0]), "=r"(f[1]), "=r"(f[2]), "=r"(f[3]) : "r"(addr));
}
__device__ __forceinline__ void mma_bf16(float* c, const uint32_t* a, const uint32_t* b) {
    asm volatile(
        "mma.sync.aligned.m16n8k16.row.col.f32.bf16.bf16.f32 "
        "{%0,%1,%2,%3}, {%4,%5,%6,%7}, {%8,%9}, {%0,%1,%2,%3};"
        : "+f"(c[0]), "+f"(c[1]), "+f"(c[2]), "+f"(c[3])
        : "r"(a[0]), "r"(a[1]), "r"(a[2]), "r"(a[3]), "r"(b[0]), "r"(b[1]));
}
__device__ __forceinline__ uint32_t pack_bf16(float x, float y) {
    __nv_bfloat16 hx = __float2bfloat16_rn(x);
    __nv_bfloat16 hy = __float2bfloat16_rn(y);
    return ((uint32_t)__bfloat16_as_ushort(hy) << 16) | __bfloat16_as_ushort(hx);
}
__device__ __forceinline__ float bf_res(float f) {
    return f - __bfloat162float(__float2bfloat16_rn(f));
}

// =============== W split (hi/lo bf16) + zero g_sumwh =======================
__global__ __launch_bounds__(256) void convw_kernel(const float* __restrict__ W) {
    if (blockIdx.x < 2) g_sumwh[blockIdx.x * 256 + threadIdx.x] = 0.0f;
    int i = blockIdx.x * 256 + threadIdx.x;      // one float4 each, 16384 total
    float4 v = ((const float4*)W)[i];
    g_Whi[i * 2]     = pack_bf16(v.x, v.y);
    g_Whi[i * 2 + 1] = pack_bf16(v.z, v.w);
    g_Wlo[i * 2]     = pack_bf16(bf_res(v.x), bf_res(v.y));
    g_Wlo[i * 2 + 1] = pack_bf16(bf_res(v.z), bf_res(v.w));
}

// =============== CSR build: warp/row, 4 loads in flight ====================
__global__ void csr_build_kernel(const float* __restrict__ adj) {
    int warp = (blockIdx.x * blockDim.x + threadIdx.x) >> 5;
    int lane = threadIdx.x & 31;
    if (warp >= N_) return;
    const float4* row = (const float4*)(adj + (size_t)warp * N_);
    int cnt = 0;
    for (int base = 0; base < N_; base += 512) {
        float4 v0 = row[(base >> 2) + lane];
        float4 v1 = row[(base >> 2) + 32 + lane];
        float4 v2 = row[(base >> 2) + 64 + lane];
        float4 v3 = row[(base >> 2) + 96 + lane];
        float c16[16] = {v0.x, v0.y, v0.z, v0.w, v1.x, v1.y, v1.z, v1.w,
                         v2.x, v2.y, v2.z, v2.w, v3.x, v3.y, v3.z, v3.w};
#pragma unroll
        for (int h = 0; h < 4; h++) {
#pragma unroll
            for (int c = 0; c < 4; c++) {
                float f = c16[h * 4 + c];
                unsigned m = __ballot_sync(0xffffffffu, f > 0.0f);
                if (f > 0.0f) {
                    int pos = cnt + __popc(m & ((1u << lane) - 1u));
                    if (pos < MAXDEG)
                        g_cols[warp * MAXDEG + pos] = base + h * 128 + lane * 4 + c;
                }
                cnt += __popc(m);
            }
        }
    }
    if (lane == 0) g_deg[warp] = cnt < MAXDEG ? cnt : MAXDEG;
}

// ============ HMMA GEMM: wh = x @ W  (M=16384, N=128, K=512) ===============
#define KC 32
#define NCH (DIN_ / KC)          // 16 chunks
#define A_STG 16384              // 128 rows * 128B
#define B_STG 16384              // hi 8KB + lo 8KB
#define SM_A 0
#define SM_B (2 * A_STG)
#define SM_SD (SM_B + 2 * B_STG)          // s_sm[128], d_sm[128]
#define SM_AV (SM_SD + 1024)              // a_s[128], a_d[128]
#define SM_CS (SM_AV + 1024)              // cs[128] column sums
#define SMEM_TOTAL (SM_CS + 512)

__device__ __forceinline__ uint32_t a_off(int r, int gran) {
    return (uint32_t)(r * 128 + ((gran ^ (r & 7)) << 4));
}
__device__ __forceinline__ uint32_t b_off2(int k, int gran) {
    return (uint32_t)(k * 256 + ((gran ^ (k & 7)) << 4));
}

__global__ __launch_bounds__(256, 1) void gemm_hmma_kernel(
    const float* __restrict__ x, const float* __restrict__ a) {
    extern __shared__ char smem[];
    const uint32_t sb = smem_u32(smem);
    const int tid = threadIdx.x;
    const int wid = tid >> 5, lane = tid & 31;
    const int wm = wid >> 1, wn = wid & 1;
    const int tig = lane & 3, grp = lane >> 2;

    float* s_sm = (float*)(smem + SM_SD);
    float* d_sm = (float*)(smem + SM_SD + 512);
    float* a_s  = (float*)(smem + SM_AV);
    float* a_d  = (float*)(smem + SM_AV + 512);
    float* cs   = (float*)(smem + SM_CS);
    if (tid < 128) {
        s_sm[tid] = 0.0f; d_sm[tid] = 0.0f; cs[tid] = 0.0f;
        a_s[tid] = a[tid]; a_d[tid] = a[DOUT_ + tid];
    }

    const int R0 = blockIdx.x * 128;
    const int arow = tid >> 1, akoff = (tid & 1) * 16;
    const float* pA = x + (size_t)(R0 + arow) * DIN_ + akoff;
    const int bk = tid >> 3, bgr = (tid & 7) * 2;
    const uint4* Whi4 = (const uint4*)g_Whi;
    const uint4* Wlo4 = (const uint4*)g_Wlo;

    float acc[2][8][4];
#pragma unroll
    for (int i = 0; i < 2; i++)
#pragma unroll
        for (int j = 0; j < 8; j++)
#pragma unroll
            for (int q = 0; q < 4; q++) acc[i][j][q] = 0.0f;

    float4 ra[4];
    uint4 rbh[2], rbl[2];
#pragma unroll
    for (int i = 0; i < 4; i++) ra[i] = *(const float4*)(pA + i * 4);
    {
        int gi = bk * 16 + bgr;
        rbh[0] = Whi4[gi];     rbh[1] = Whi4[gi + 1];
        rbl[0] = Wlo4[gi];     rbl[1] = Wlo4[gi + 1];
    }

    for (int c = 0; c < NCH; c++) {
        const int buf = c & 1;
        char* Abuf = smem + SM_A + buf * A_STG;
        char* Bhi  = smem + SM_B + buf * B_STG;
        char* Blo  = Bhi + 8192;

        {
            const float* fa = (const float*)ra;
#pragma unroll
            for (int p = 0; p < 8; p++) {
                float f0 = fa[2 * p], f1 = fa[2 * p + 1];
                uint32_t hv = pack_bf16(f0, f1);
                uint32_t lv = pack_bf16(bf_res(f0), bf_res(f1));
                int kl = akoff + 2 * p;
                int gr = kl >> 3, wi = (kl & 7) * 2;
                *(uint32_t*)(Abuf + a_off(arow, gr) + wi)     = hv;
                *(uint32_t*)(Abuf + a_off(arow, gr + 4) + wi) = lv;
            }
            *(uint4*)(Bhi + b_off2(bk, bgr))     = rbh[0];
            *(uint4*)(Bhi + b_off2(bk, bgr + 1)) = rbh[1];
            *(uint4*)(Blo + b_off2(bk, bgr))     = rbl[0];
            *(uint4*)(Blo + b_off2(bk, bgr + 1)) = rbl[1];
        }
        __syncthreads();

        if (c + 1 < NCH) {
            const float* qA = pA + (c + 1) * KC;
#pragma unroll
            for (int i = 0; i < 4; i++) ra[i] = *(const float4*)(qA + i * 4);
            int gi = (c + 1) * 512 + bk * 16 + bgr;
            rbh[0] = Whi4[gi];     rbh[1] = Whi4[gi + 1];
            rbl[0] = Wlo4[gi];     rbl[1] = Wlo4[gi + 1];
        }

        const uint32_t Abase = sb + SM_A + buf * A_STG;
        const uint32_t BhiB  = sb + SM_B + buf * B_STG;
        const uint32_t BloB  = BhiB + 8192;
#pragma unroll
        for (int ks = 0; ks < 2; ks++) {
            uint32_t ahi[2][4], alo[2][4];
#pragma unroll
            for (int mt = 0; mt < 2; mt++) {
                int R = wm * 32 + mt * 16 + (lane & 15);
                int gh = 2 * ks + (lane >> 4);
                ldm_x4(ahi[mt], Abase + a_off(R, gh));
                ldm_x4(alo[mt], Abase + a_off(R, gh + 4));
            }
            int kk = 16 * ks + (lane & 15);
#pragma unroll
            for (int ntp = 0; ntp < 4; ntp++) {
                int gn = wn * 8 + ntp * 2 + (lane >> 4);
                uint32_t bhi[4], blo[4];
                ldm_x4t(bhi, BhiB + b_off2(kk, gn));
                ldm_x4t(blo, BloB + b_off2(kk, gn));
#pragma unroll
                for (int mt = 0; mt < 2; mt++) {
                    mma_bf16(acc[mt][ntp * 2],     ahi[mt], bhi);
                    mma_bf16(acc[mt][ntp * 2 + 1], ahi[mt], bhi + 2);
                    mma_bf16(acc[mt][ntp * 2],     ahi[mt], blo);
                    mma_bf16(acc[mt][ntp * 2 + 1], ahi[mt], blo + 2);
                    mma_bf16(acc[mt][ntp * 2],     alo[mt], bhi);
                    mma_bf16(acc[mt][ntp * 2 + 1], alo[mt], bhi + 2);
                }
            }
        }
        __syncthreads();
    }

    // ---- epilogue: store wh, fused s/d dots + column sums ----
    float sacc[2][2] = {{0, 0}, {0, 0}}, dacc[2][2] = {{0, 0}, {0, 0}};
#pragma unroll
    for (int mt = 0; mt < 2; mt++) {
        int rbase = R0 + wm * 32 + mt * 16 + grp;
#pragma unroll
        for (int nt = 0; nt < 8; nt++) {
            int col = wn * 64 + nt * 8 + tig * 2;
            float* cf = acc[mt][nt];
            sacc[mt][0] += cf[0] * a_s[col] + cf[1] * a_s[col + 1];
            sacc[mt][1] += cf[2] * a_s[col] + cf[3] * a_s[col + 1];
            dacc[mt][0] += cf[0] * a_d[col] + cf[1] * a_d[col + 1];
            dacc[mt][1] += cf[2] * a_d[col] + cf[3] * a_d[col + 1];
            *(float2*)&g_wh[(size_t)rbase * DOUT_ + col]       = make_float2(cf[0], cf[1]);
            *(float2*)&g_wh[(size_t)(rbase + 8) * DOUT_ + col] = make_float2(cf[2], cf[3]);

            float v0 = cf[0] + cf[2];
            float v1 = cf[1] + cf[3];
#pragma unroll
            for (int off = 16; off >= 4; off >>= 1) {
                v0 += __shfl_down_sync(0xffffffffu, v0, off);
                v1 += __shfl_down_sync(0xffffffffu, v1, off);
            }
            if (lane < 4) {
                atomicAdd(&cs[col], v0);
                atomicAdd(&cs[col + 1], v1);
            }
        }
    }
#pragma unroll
    for (int mt = 0; mt < 2; mt++)
#pragma unroll
        for (int h = 0; h < 2; h++) {
            sacc[mt][h] += __shfl_xor_sync(0xffffffffu, sacc[mt][h], 1);
            sacc[mt][h] += __shfl_xor_sync(0xffffffffu, sacc[mt][h], 2);
            dacc[mt][h] += __shfl_xor_sync(0xffffffffu, dacc[mt][h], 1);
            dacc[mt][h] += __shfl_xor_sync(0xffffffffu, dacc[mt][h], 2);
        }
    if (tig == 0) {
#pragma unroll
        for (int mt = 0; mt < 2; mt++) {
            int r = wm * 32 + mt * 16 + grp;
            atomicAdd(&s_sm[r], sacc[mt][0]);
            atomicAdd(&s_sm[r + 8], sacc[mt][1]);
            atomicAdd(&d_sm[r], dacc[mt][0]);
            atomicAdd(&d_sm[r + 8], dacc[mt][1]);
        }
    }
    __syncthreads();
    if (tid < 128) {
        g_s[R0 + tid] = s_sm[tid];
        g_d[R0 + tid] = d_sm[tid];
        int b = R0 / N_;
        atomicAdd(&g_sumwh[b * DOUT_ + tid], cs[tid]);
    }
}

// ---------------- attention SpMM (batched, warp per row) ----------------
__global__ __launch_bounds__(256) void attn_kernel() {
    __shared__ float sh_p[8][MAXDEG];
    __shared__ int   sh_j[8][MAXDEG];
    int gw = (blockIdx.x * blockDim.x + threadIdx.x) >> 5;
    int lane = threadIdx.x & 31;
    int w = (threadIdx.x >> 5);
    if (gw >= B_ * N_) return;
    int b = gw / N_, i = gw % N_;
    int deg = g_deg[i];

    float4* outr = (float4*)&g_out[(size_t)gw * DOUT_];

    if (deg == 0) {
        const float4* sw = (const float4*)&g_sumwh[b * DOUT_];
        float4 m = sw[lane];
        float inv = 1.0f / (float)N_;
        outr[lane] = make_float4(m.x * inv, m.y * inv, m.z * inv, m.w * inv);
        return;
    }

    float si = g_s[gw];
    float mx = NEG_BIG;
    for (int t = lane; t < deg; t += 32) {
        int j = g_cols[i * MAXDEG + t];
        float e = si + g_d[(size_t)b * N_ + j];
        e = e > 0.0f ? e : 0.01f * e;
        sh_j[w][t] = j;
        sh_p[w][t] = e;
        mx = fmaxf(mx, e);
    }
#pragma unroll
    for (int off = 16; off > 0; off >>= 1)
        mx = fmaxf(mx, __shfl_xor_sync(0xffffffffu, mx, off));
    __syncwarp();

    float se = 0.0f;
    for (int t = lane; t < deg; t += 32) {
        float p = expf(sh_p[w][t] - mx);
        sh_p[w][t] = p;
        se += p;
    }
#pragma unroll
    for (int off = 16; off > 0; off >>= 1)
        se += __shfl_xor_sync(0xffffffffu, se, off);
    float inv = 1.0f / se;
    __syncwarp();

    const float4* whb = (const float4*)&g_wh[(size_t)b * N_ * DOUT_];
    float4 acc0 = make_float4(0.f, 0.f, 0.f, 0.f);
    float4 acc1 = make_float4(0.f, 0.f, 0.f, 0.f);
    float4 acc2 = make_float4(0.f, 0.f, 0.f, 0.f);
    float4 acc3 = make_float4(0.f, 0.f, 0.f, 0.f);
    int k = 0;
    for (; k + 4 <= deg; k += 4) {
        float p0 = sh_p[w][k] * inv,     p1 = sh_p[w][k + 1] * inv;
        float p2 = sh_p[w][k + 2] * inv, p3 = sh_p[w][k + 3] * inv;
        int j0 = sh_j[w][k],     j1 = sh_j[w][k + 1];
        int j2 = sh_j[w][k + 2], j3 = sh_j[w][k + 3];
        float4 v0 = whb[(size_t)j0 * 32 + lane];
        float4 v1 = whb[(size_t)j1 * 32 + lane];
        float4 v2 = whb[(size_t)j2 * 32 + lane];
        float4 v3 = whb[(size_t)j3 * 32 + lane];
        acc0.x += p0 * v0.x; acc0.y += p0 * v0.y; acc0.z += p0 * v0.z; acc0.w += p0 * v0.w;
        acc1.x += p1 * v1.x; acc1.y += p1 * v1.y; acc1.z += p1 * v1.z; acc1.w += p1 * v1.w;
        acc2.x += p2 * v2.x; acc2.y += p2 * v2.y; acc2.z += p2 * v2.z; acc2.w += p2 * v2.w;
        acc3.x += p3 * v3.x; acc3.y += p3 * v3.y; acc3.z += p3 * v3.z; acc3.w += p3 * v3.w;
    }
    for (; k < deg; k++) {
        float p0 = sh_p[w][k] * inv;
        float4 v0 = whb[(size_t)sh_j[w][k] * 32 + lane];
        acc0.x += p0 * v0.x; acc0.y += p0 * v0.y; acc0.z += p0 * v0.z; acc0.w += p0 * v0.w;
    }
    outr[lane] = make_float4(acc0.x + acc1.x + acc2.x + acc3.x,
                             acc0.y + acc1.y + acc2.y + acc3.y,
                             acc0.z + acc1.z + acc2.z + acc3.z,
                             acc0.w + acc1.w + acc2.w + acc3.w);
}

// ---------------- final: y = relu(adj @ out) (batched) ----------------
__global__ __launch_bounds__(256) void final_kernel(float* __restrict__ y) {
    int gw = (blockIdx.x * blockDim.x + threadIdx.x) >> 5;
    int lane = threadIdx.x & 31;
    if (gw >= B_ * N_) return;
    int b = gw / N_, i = gw % N_;
    int deg = g_deg[i];

    const float4* outb = (const float4*)&g_out[(size_t)b * N_ * DOUT_];
    float4 acc0 = make_float4(0.f, 0.f, 0.f, 0.f);
    float4 acc1 = make_float4(0.f, 0.f, 0.f, 0.f);
    float4 acc2 = make_float4(0.f, 0.f, 0.f, 0.f);
    float4 acc3 = make_float4(0.f, 0.f, 0.f, 0.f);
    int k = 0;
    for (; k + 4 <= deg; k += 4) {
        int j0 = g_cols[i * MAXDEG + k],     j1 = g_cols[i * MAXDEG + k + 1];
        int j2 = g_cols[i * MAXDEG + k + 2], j3 = g_cols[i * MAXDEG + k + 3];
        float4 v0 = outb[(size_t)j0 * 32 + lane];
        float4 v1 = outb[(size_t)j1 * 32 + lane];
        float4 v2 = outb[(size_t)j2 * 32 + lane];
        float4 v3 = outb[(size_t)j3 * 32 + lane];
        acc0.x += v0.x; acc0.y += v0.y; acc0.z += v0.z; acc0.w += v0.w;
        acc1.x += v1.x; acc1.y += v1.y; acc1.z += v1.z; acc1.w += v1.w;
        acc2.x += v2.x; acc2.y += v2.y; acc2.z += v2.z; acc2.w += v2.w;
        acc3.x += v3.x; acc3.y += v3.y; acc3.z += v3.z; acc3.w += v3.w;
    }
    for (; k < deg; k++) {
        float4 v0 = outb[(size_t)g_cols[i * MAXDEG + k] * 32 + lane];
        acc0.x += v0.x; acc0.y += v0.y; acc0.z += v0.z; acc0.w += v0.w;
    }
    float4 r = make_float4(fmaxf(acc0.x + acc1.x + acc2.x + acc3.x, 0.f),
                           fmaxf(acc0.y + acc1.y + acc2.y + acc3.y, 0.f),
                           fmaxf(acc0.z + acc1.z + acc2.z + acc3.z, 0.f),
                           fmaxf(acc0.w + acc1.w + acc2.w + acc3.w, 0.f));
    ((float4*)&y[(size_t)gw * DOUT_])[lane] = r;
}

// ---------------- launch ----------------
extern "C" void kernel_launch(void* const* d_in, const int* in_sizes, int n_in,
                              void* d_out, int out_size) {
    const float* x   = (const float*)d_in[0];  // (B, N, DIN)
    const float* adj = (const float*)d_in[1];  // (N, N)
    const float* wts = (const float*)d_in[2];  // (DIN, DOUT)
    const float* a   = (const float*)d_in[3];  // (2*DOUT, 1)
    float* y = (float*)d_out;

    static cudaStream_t s2;
    static cudaEvent_t evA, evC;
    static int inited = 0;
    if (!inited) {
        cudaFuncSetAttribute(gemm_hmma_kernel,
                             cudaFuncAttributeMaxDynamicSharedMemorySize, SMEM_TOTAL);
        cudaStreamCreateWithFlags(&s2, cudaStreamNonBlocking);
        cudaEventCreateWithFlags(&evA, cudaEventDisableTiming);
        cudaEventCreateWithFlags(&evC, cudaEventDisableTiming);
        inited = 1;
    }
    cudaStream_t s0 = 0;

    // fork: csr on s2 overlaps convW+GEMM on s0; join before attn
    cudaEventRecord(evA, s0);
    cudaStreamWaitEvent(s2, evA, 0);
    csr_build_kernel<<<N_ / 8, 256, 0, s2>>>(adj);
    cudaEventRecord(evC, s2);

    convw_kernel<<<DIN_ * DOUT_ / 1024, 256, 0, s0>>>(wts);
    gemm_hmma_kernel<<<(B_ * N_) / 128, 256, SMEM_TOTAL, s0>>>(x, a);
    cudaStreamWaitEvent(s0, evC, 0);

    attn_kernel<<<(B_ * N_) / 8, 256, 0, s0>>>();
    final_kernel<<<(B_ * N_) / 8, 256, 0, s0>>>(y);
}

// round 7
// speedup vs baseline: 1.2323x; 1.0867x over previous
#include <cuda_runtime.h>
#include <cuda_bf16.h>
#include <cuda_fp16.h>
#include <math.h>
#include <stdint.h>

#define B_    4
#define N_    4096
#define DIN_  512
#define DOUT_ 128
#define MAXDEG 256
#define NEG_BIG -1e30f

// ---------------- scratch (static device memory; no allocs) ----------------
__device__ __half g_whh[B_ * N_ * DOUT_];   // x @ W (fp16, gather-only)  4 MB
__device__ __half g_outh[B_ * N_ * DOUT_];  // att @ wh (fp16)            4 MB
__device__ float g_s[B_ * N_];              // wh @ a_src
__device__ float g_d[B_ * N_];              // wh @ a_dst
__device__ float g_sumwh[B_ * DOUT_];       // per-graph colsum (deg==0 fallback)
__device__ int   g_cols[N_ * MAXDEG];
__device__ int   g_deg[N_];
__device__ uint32_t g_Whi[DIN_ * DOUT_ / 2];  // W split hi (bf16x2 packed)
__device__ uint32_t g_Wlo[DIN_ * DOUT_ / 2];  // W split lo

// ============================ helpers =======================================
__device__ __forceinline__ uint32_t smem_u32(const void* p) {
    uint32_t a;
    asm("{ .reg .u64 t; cvta.to.shared.u64 t, %1; cvt.u32.u64 %0, t; }" : "=r"(a) : "l"(p));
    return a;
}
__device__ __forceinline__ void ldm_x4(uint32_t* f, uint32_t addr) {
    asm volatile("ldmatrix.sync.aligned.m8n8.x4.shared.b16 {%0,%1,%2,%3}, [%4];"
                 : "=r"(f[0]), "=r"(f[1]), "=r"(f[2]), "=r"(f[3]) : "r"(addr));
}
__device__ __forceinline__ void ldm_x4t(uint32_t* f, uint32_t addr) {
    asm volatile("ldmatrix.sync.aligned.m8n8.x4.trans.shared.b16 {%0,%1,%2,%3}, [%4];"
                 : "=r"(f[0]), "=r"(f[1]), "=r"(f[2]), "=r"(f[3]) : "r"(addr));
}
__device__ __forceinline__ void mma_bf16(float* c, const uint32_t* a, const uint32_t* b) {
    asm volatile(
        "mma.sync.aligned.m16n8k16.row.col.f32.bf16.bf16.f32 "
        "{%0,%1,%2,%3}, {%4,%5,%6,%7}, {%8,%9}, {%0,%1,%2,%3};"
        : "+f"(c[0]), "+f"(c[1]), "+f"(c[2]), "+f"(c[3])
        : "r"(a[0]), "r"(a[1]), "r"(a[2]), "r"(a[3]), "r"(b[0]), "r"(b[1]));
}
__device__ __forceinline__ uint32_t pack_bf16(float x, float y) {
    __nv_bfloat16 hx = __float2bfloat16_rn(x);
    __nv_bfloat16 hy = __float2bfloat16_rn(y);
    return ((uint32_t)__bfloat16_as_ushort(hy) << 16) | __bfloat16_as_ushort(hx);
}
__device__ __forceinline__ float bf_res(float f) {
    return f - __bfloat162float(__float2bfloat16_rn(f));
}

// =============== W split (hi/lo bf16) + zero g_sumwh =======================
__global__ __launch_bounds__(256) void convw_kernel(const float* __restrict__ W) {
    if (blockIdx.x < 2) g_sumwh[blockIdx.x * 256 + threadIdx.x] = 0.0f;
    int i = blockIdx.x * 256 + threadIdx.x;      // one float4 each, 16384 total
    float4 v = ((const float4*)W)[i];
    g_Whi[i * 2]     = pack_bf16(v.x, v.y);
    g_Whi[i * 2 + 1] = pack_bf16(v.z, v.w);
    g_Wlo[i * 2]     = pack_bf16(bf_res(v.x), bf_res(v.y));
    g_Wlo[i * 2 + 1] = pack_bf16(bf_res(v.z), bf_res(v.w));
}

// =============== CSR build: warp/row, 4 loads in flight ====================
__global__ void csr_build_kernel(const float* __restrict__ adj) {
    int warp = (blockIdx.x * blockDim.x + threadIdx.x) >> 5;
    int lane = threadIdx.x & 31;
    if (warp >= N_) return;
    const float4* row = (const float4*)(adj + (size_t)warp * N_);
    int cnt = 0;
    for (int base = 0; base < N_; base += 512) {
        float4 v0 = row[(base >> 2) + lane];
        float4 v1 = row[(base >> 2) + 32 + lane];
        float4 v2 = row[(base >> 2) + 64 + lane];
        float4 v3 = row[(base >> 2) + 96 + lane];
        float c16[16] = {v0.x, v0.y, v0.z, v0.w, v1.x, v1.y, v1.z, v1.w,
                         v2.x, v2.y, v2.z, v2.w, v3.x, v3.y, v3.z, v3.w};
#pragma unroll
        for (int h = 0; h < 4; h++) {
#pragma unroll
            for (int c = 0; c < 4; c++) {
                float f = c16[h * 4 + c];
                unsigned m = __ballot_sync(0xffffffffu, f > 0.0f);
                if (f > 0.0f) {
                    int pos = cnt + __popc(m & ((1u << lane) - 1u));
                    if (pos < MAXDEG)
                        g_cols[warp * MAXDEG + pos] = base + h * 128 + lane * 4 + c;
                }
                cnt += __popc(m);
            }
        }
    }
    if (lane == 0) g_deg[warp] = cnt < MAXDEG ? cnt : MAXDEG;
}

// ============ HMMA GEMM: wh = x @ W  (M=16384, N=128, K=512) ===============
#define KC 32
#define NCH (DIN_ / KC)          // 16 chunks
#define A_STG 16384              // 128 rows * 128B
#define B_STG 16384              // hi 8KB + lo 8KB
#define SM_A 0
#define SM_B (2 * A_STG)
#define SM_SD (SM_B + 2 * B_STG)          // s_sm[128], d_sm[128]
#define SM_AV (SM_SD + 1024)              // a_s[128], a_d[128]
#define SM_CS (SM_AV + 1024)              // cs[128] column sums
#define SMEM_TOTAL (SM_CS + 512)

__device__ __forceinline__ uint32_t a_off(int r, int gran) {
    return (uint32_t)(r * 128 + ((gran ^ (r & 7)) << 4));
}
__device__ __forceinline__ uint32_t b_off2(int k, int gran) {
    return (uint32_t)(k * 256 + ((gran ^ (k & 7)) << 4));
}

__global__ __launch_bounds__(256, 1) void gemm_hmma_kernel(
    const float* __restrict__ x, const float* __restrict__ a) {
    extern __shared__ char smem[];
    const uint32_t sb = smem_u32(smem);
    const int tid = threadIdx.x;
    const int wid = tid >> 5, lane = tid & 31;
    const int wm = wid >> 1, wn = wid & 1;
    const int tig = lane & 3, grp = lane >> 2;

    float* s_sm = (float*)(smem + SM_SD);
    float* d_sm = (float*)(smem + SM_SD + 512);
    float* a_s  = (float*)(smem + SM_AV);
    float* a_d  = (float*)(smem + SM_AV + 512);
    float* cs   = (float*)(smem + SM_CS);
    if (tid < 128) {
        s_sm[tid] = 0.0f; d_sm[tid] = 0.0f; cs[tid] = 0.0f;
        a_s[tid] = a[tid]; a_d[tid] = a[DOUT_ + tid];
    }

    const int R0 = blockIdx.x * 128;
    const int arow = tid >> 1, akoff = (tid & 1) * 16;
    const float* pA = x + (size_t)(R0 + arow) * DIN_ + akoff;
    const int bk = tid >> 3, bgr = (tid & 7) * 2;
    const uint4* Whi4 = (const uint4*)g_Whi;
    const uint4* Wlo4 = (const uint4*)g_Wlo;

    float acc[2][8][4];
#pragma unroll
    for (int i = 0; i < 2; i++)
#pragma unroll
        for (int j = 0; j < 8; j++)
#pragma unroll
            for (int q = 0; q < 4; q++) acc[i][j][q] = 0.0f;

    float4 ra[4];
    uint4 rbh[2], rbl[2];
#pragma unroll
    for (int i = 0; i < 4; i++) ra[i] = *(const float4*)(pA + i * 4);
    {
        int gi = bk * 16 + bgr;
        rbh[0] = Whi4[gi];     rbh[1] = Whi4[gi + 1];
        rbl[0] = Wlo4[gi];     rbl[1] = Wlo4[gi + 1];
    }

    for (int c = 0; c < NCH; c++) {
        const int buf = c & 1;
        char* Abuf = smem + SM_A + buf * A_STG;
        char* Bhi  = smem + SM_B + buf * B_STG;
        char* Blo  = Bhi + 8192;

        {
            const float* fa = (const float*)ra;
#pragma unroll
            for (int p = 0; p < 8; p++) {
                float f0 = fa[2 * p], f1 = fa[2 * p + 1];
                uint32_t hv = pack_bf16(f0, f1);
                uint32_t lv = pack_bf16(bf_res(f0), bf_res(f1));
                int kl = akoff + 2 * p;
                int gr = kl >> 3, wi = (kl & 7) * 2;
                *(uint32_t*)(Abuf + a_off(arow, gr) + wi)     = hv;
                *(uint32_t*)(Abuf + a_off(arow, gr + 4) + wi) = lv;
            }
            *(uint4*)(Bhi + b_off2(bk, bgr))     = rbh[0];
            *(uint4*)(Bhi + b_off2(bk, bgr + 1)) = rbh[1];
            *(uint4*)(Blo + b_off2(bk, bgr))     = rbl[0];
            *(uint4*)(Blo + b_off2(bk, bgr + 1)) = rbl[1];
        }
        __syncthreads();

        if (c + 1 < NCH) {
            const float* qA = pA + (c + 1) * KC;
#pragma unroll
            for (int i = 0; i < 4; i++) ra[i] = *(const float4*)(qA + i * 4);
            int gi = (c + 1) * 512 + bk * 16 + bgr;
            rbh[0] = Whi4[gi];     rbh[1] = Whi4[gi + 1];
            rbl[0] = Wlo4[gi];     rbl[1] = Wlo4[gi + 1];
        }

        const uint32_t Abase = sb + SM_A + buf * A_STG;
        const uint32_t BhiB  = sb + SM_B + buf * B_STG;
        const uint32_t BloB  = BhiB + 8192;
#pragma unroll
        for (int ks = 0; ks < 2; ks++) {
            uint32_t ahi[2][4], alo[2][4];
#pragma unroll
            for (int mt = 0; mt < 2; mt++) {
                int R = wm * 32 + mt * 16 + (lane & 15);
                int gh = 2 * ks + (lane >> 4);
                ldm_x4(ahi[mt], Abase + a_off(R, gh));
                ldm_x4(alo[mt], Abase + a_off(R, gh + 4));
            }
            int kk = 16 * ks + (lane & 15);
#pragma unroll
            for (int ntp = 0; ntp < 4; ntp++) {
                int gn = wn * 8 + ntp * 2 + (lane >> 4);
                uint32_t bhi[4], blo[4];
                ldm_x4t(bhi, BhiB + b_off2(kk, gn));
                ldm_x4t(blo, BloB + b_off2(kk, gn));
#pragma unroll
                for (int mt = 0; mt < 2; mt++) {
                    mma_bf16(acc[mt][ntp * 2],     ahi[mt], bhi);
                    mma_bf16(acc[mt][ntp * 2 + 1], ahi[mt], bhi + 2);
                    mma_bf16(acc[mt][ntp * 2],     ahi[mt], blo);
                    mma_bf16(acc[mt][ntp * 2 + 1], ahi[mt], blo + 2);
                    mma_bf16(acc[mt][ntp * 2],     alo[mt], bhi);
                    mma_bf16(acc[mt][ntp * 2 + 1], alo[mt], bhi + 2);
                }
            }
        }
        __syncthreads();
    }

    // ---- epilogue: store wh (fp16), fused s/d dots + column sums ----
    float sacc[2][2] = {{0, 0}, {0, 0}}, dacc[2][2] = {{0, 0}, {0, 0}};
#pragma unroll
    for (int mt = 0; mt < 2; mt++) {
        int rbase = R0 + wm * 32 + mt * 16 + grp;
#pragma unroll
        for (int nt = 0; nt < 8; nt++) {
            int col = wn * 64 + nt * 8 + tig * 2;
            float* cf = acc[mt][nt];
            sacc[mt][0] += cf[0] * a_s[col] + cf[1] * a_s[col + 1];
            sacc[mt][1] += cf[2] * a_s[col] + cf[3] * a_s[col + 1];
            dacc[mt][0] += cf[0] * a_d[col] + cf[1] * a_d[col + 1];
            dacc[mt][1] += cf[2] * a_d[col] + cf[3] * a_d[col + 1];
            *(__half2*)&g_whh[(size_t)rbase * DOUT_ + col] =
                __float22half2_rn(make_float2(cf[0], cf[1]));
            *(__half2*)&g_whh[(size_t)(rbase + 8) * DOUT_ + col] =
                __float22half2_rn(make_float2(cf[2], cf[3]));

            float v0 = cf[0] + cf[2];
            float v1 = cf[1] + cf[3];
#pragma unroll
            for (int off = 16; off >= 4; off >>= 1) {
                v0 += __shfl_down_sync(0xffffffffu, v0, off);
                v1 += __shfl_down_sync(0xffffffffu, v1, off);
            }
            if (lane < 4) {
                atomicAdd(&cs[col], v0);
                atomicAdd(&cs[col + 1], v1);
            }
        }
    }
#pragma unroll
    for (int mt = 0; mt < 2; mt++)
#pragma unroll
        for (int h = 0; h < 2; h++) {
            sacc[mt][h] += __shfl_xor_sync(0xffffffffu, sacc[mt][h], 1);
            sacc[mt][h] += __shfl_xor_sync(0xffffffffu, sacc[mt][h], 2);
            dacc[mt][h] += __shfl_xor_sync(0xffffffffu, dacc[mt][h], 1);
            dacc[mt][h] += __shfl_xor_sync(0xffffffffu, dacc[mt][h], 2);
        }
    if (tig == 0) {
#pragma unroll
        for (int mt = 0; mt < 2; mt++) {
            int r = wm * 32 + mt * 16 + grp;
            atomicAdd(&s_sm[r], sacc[mt][0]);
            atomicAdd(&s_sm[r + 8], sacc[mt][1]);
            atomicAdd(&d_sm[r], dacc[mt][0]);
            atomicAdd(&d_sm[r + 8], dacc[mt][1]);
        }
    }
    __syncthreads();
    if (tid < 128) {
        g_s[R0 + tid] = s_sm[tid];
        g_d[R0 + tid] = d_sm[tid];
        int b = R0 / N_;
        atomicAdd(&g_sumwh[b * DOUT_ + tid], cs[tid]);
    }
}

// ---------------- attention SpMM (batched, warp per row, fp16 gather) ------
__global__ __launch_bounds__(256) void attn_kernel() {
    __shared__ float sh_p[8][MAXDEG];
    __shared__ int   sh_j[8][MAXDEG];
    int gw = (blockIdx.x * blockDim.x + threadIdx.x) >> 5;
    int lane = threadIdx.x & 31;
    int w = (threadIdx.x >> 5);
    if (gw >= B_ * N_) return;
    int b = gw / N_, i = gw % N_;
    int deg = g_deg[i];

    uint2* outr = (uint2*)&g_outh[(size_t)gw * DOUT_];   // lane owns cols 4l..4l+3

    if (deg == 0) {
        const float4* sw = (const float4*)&g_sumwh[b * DOUT_];
        float4 m = sw[lane];
        float inv = 1.0f / (float)N_;
        uint2 o;
        *(__half2*)&o.x = __float22half2_rn(make_float2(m.x * inv, m.y * inv));
        *(__half2*)&o.y = __float22half2_rn(make_float2(m.z * inv, m.w * inv));
        outr[lane] = o;
        return;
    }

    float si = g_s[gw];
    float mx = NEG_BIG;
    for (int t = lane; t < deg; t += 32) {
        int j = g_cols[i * MAXDEG + t];
        float e = si + g_d[(size_t)b * N_ + j];
        e = e > 0.0f ? e : 0.01f * e;
        sh_j[w][t] = j;
        sh_p[w][t] = e;
        mx = fmaxf(mx, e);
    }
#pragma unroll
    for (int off = 16; off > 0; off >>= 1)
        mx = fmaxf(mx, __shfl_xor_sync(0xffffffffu, mx, off));
    __syncwarp();

    float se = 0.0f;
    for (int t = lane; t < deg; t += 32) {
        float p = __expf(sh_p[w][t] - mx);
        sh_p[w][t] = p;
        se += p;
    }
#pragma unroll
    for (int off = 16; off > 0; off >>= 1)
        se += __shfl_xor_sync(0xffffffffu, se, off);
    float inv = 1.0f / se;
    __syncwarp();

    const uint2* whb = (const uint2*)&g_whh[(size_t)b * N_ * DOUT_];
    float a0 = 0.f, a1 = 0.f, a2 = 0.f, a3 = 0.f;
    int k = 0;
    for (; k + 8 <= deg; k += 8) {
        uint2 v[8]; float p[8];
#pragma unroll
        for (int u = 0; u < 8; u++) {
            p[u] = sh_p[w][k + u] * inv;
            v[u] = whb[(size_t)sh_j[w][k + u] * 32 + lane];
        }
#pragma unroll
        for (int u = 0; u < 8; u++) {
            float2 f0 = __half22float2(*(__half2*)&v[u].x);
            float2 f1 = __half22float2(*(__half2*)&v[u].y);
            a0 += p[u] * f0.x; a1 += p[u] * f0.y;
            a2 += p[u] * f1.x; a3 += p[u] * f1.y;
        }
    }
    for (; k < deg; k++) {
        float p0 = sh_p[w][k] * inv;
        uint2 v = whb[(size_t)sh_j[w][k] * 32 + lane];
        float2 f0 = __half22float2(*(__half2*)&v.x);
        float2 f1 = __half22float2(*(__half2*)&v.y);
        a0 += p0 * f0.x; a1 += p0 * f0.y; a2 += p0 * f1.x; a3 += p0 * f1.y;
    }
    uint2 o;
    *(__half2*)&o.x = __float22half2_rn(make_float2(a0, a1));
    *(__half2*)&o.y = __float22half2_rn(make_float2(a2, a3));
    outr[lane] = o;
}

// ---------------- final: y = relu(adj @ out) (batched, fp16 gather) --------
__global__ __launch_bounds__(256) void final_kernel(float* __restrict__ y) {
    int gw = (blockIdx.x * blockDim.x + threadIdx.x) >> 5;
    int lane = threadIdx.x & 31;
    if (gw >= B_ * N_) return;
    int b = gw / N_, i = gw % N_;
    int deg = g_deg[i];

    const uint2* outb = (const uint2*)&g_outh[(size_t)b * N_ * DOUT_];
    float a0 = 0.f, a1 = 0.f, a2 = 0.f, a3 = 0.f;
    int k = 0;
    for (; k + 8 <= deg; k += 8) {
        uint2 v[8];
#pragma unroll
        for (int u = 0; u < 8; u++)
            v[u] = outb[(size_t)g_cols[i * MAXDEG + k + u] * 32 + lane];
#pragma unroll
        for (int u = 0; u < 8; u++) {
            float2 f0 = __half22float2(*(__half2*)&v[u].x);
            float2 f1 = __half22float2(*(__half2*)&v[u].y);
            a0 += f0.x; a1 += f0.y; a2 += f1.x; a3 += f1.y;
        }
    }
    for (; k < deg; k++) {
        uint2 v = outb[(size_t)g_cols[i * MAXDEG + k] * 32 + lane];
        float2 f0 = __half22float2(*(__half2*)&v.x);
        float2 f1 = __half22float2(*(__half2*)&v.y);
        a0 += f0.x; a1 += f0.y; a2 += f1.x; a3 += f1.y;
    }
    float4 r = make_float4(fmaxf(a0, 0.f), fmaxf(a1, 0.f),
                           fmaxf(a2, 0.f), fmaxf(a3, 0.f));
    ((float4*)&y[(size_t)gw * DOUT_])[lane] = r;
}

// ---------------- launch ----------------
extern "C" void kernel_launch(void* const* d_in, const int* in_sizes, int n_in,
                              void* d_out, int out_size) {
    const float* x   = (const float*)d_in[0];  // (B, N, DIN)
    const float* adj = (const float*)d_in[1];  // (N, N)
    const float* wts = (const float*)d_in[2];  // (DIN, DOUT)
    const float* a   = (const float*)d_in[3];  // (2*DOUT, 1)
    float* y = (float*)d_out;

    static cudaStream_t s2;
    static cudaEvent_t evA, evC;
    static int inited = 0;
    if (!inited) {
        cudaFuncSetAttribute(gemm_hmma_kernel,
                             cudaFuncAttributeMaxDynamicSharedMemorySize, SMEM_TOTAL);
        cudaStreamCreateWithFlags(&s2, cudaStreamNonBlocking);
        cudaEventCreateWithFlags(&evA, cudaEventDisableTiming);
        cudaEventCreateWithFlags(&evC, cudaEventDisableTiming);
        inited = 1;
    }
    cudaStream_t s0 = 0;

    // fork: csr on s2 overlaps convW+GEMM on s0; join before attn
    cudaEventRecord(evA, s0);
    cudaStreamWaitEvent(s2, evA, 0);
    csr_build_kernel<<<N_ / 8, 256, 0, s2>>>(adj);
    cudaEventRecord(evC, s2);

    convw_kernel<<<DIN_ * DOUT_ / 1024, 256, 0, s0>>>(wts);
    gemm_hmma_kernel<<<(B_ * N_) / 128, 256, SMEM_TOTAL, s0>>>(x, a);
    cudaStreamWaitEvent(s0, evC, 0);

    attn_kernel<<<(B_ * N_) / 8, 256, 0, s0>>>();
    final_kernel<<<(B_ * N_) / 8, 256, 0, s0>>>(y);
}

// round 8
// speedup vs baseline: 1.2619x; 1.0240x over previous
#include <cuda_runtime.h>
#include <cuda_bf16.h>
#include <cuda_fp16.h>
#include <math.h>
#include <stdint.h>

#define B_    4
#define N_    4096
#define DIN_  512
#define DOUT_ 128
#define MAXDEG 256
#define NEG_BIG -1e30f

// ---------------- scratch (static device memory; no allocs) ----------------
__device__ __half g_whh[B_ * N_ * DOUT_];   // x @ W (fp16, gather-only)  4 MB
__device__ __half g_outh[B_ * N_ * DOUT_];  // att @ wh (fp16)            4 MB
__device__ float g_sT[N_ * 4];              // s transposed [i][b]
__device__ float g_dT[N_ * 4];              // d transposed [i][b]
__device__ float g_sumwh[B_ * DOUT_];       // per-graph colsum (deg==0 fallback)
__device__ int   g_cols[N_ * MAXDEG];
__device__ int   g_deg[N_];
__device__ uint32_t g_Whi[DIN_ * DOUT_ / 2];  // W split hi (bf16x2 packed)
__device__ uint32_t g_Wlo[DIN_ * DOUT_ / 2];  // W split lo

// ============================ helpers =======================================
__device__ __forceinline__ uint32_t smem_u32(const void* p) {
    uint32_t a;
    asm("{ .reg .u64 t; cvta.to.shared.u64 t, %1; cvt.u32.u64 %0, t; }" : "=r"(a) : "l"(p));
    return a;
}
__device__ __forceinline__ void ldm_x4(uint32_t* f, uint32_t addr) {
    asm volatile("ldmatrix.sync.aligned.m8n8.x4.shared.b16 {%0,%1,%2,%3}, [%4];"
                 : "=r"(f[0]), "=r"(f[1]), "=r"(f[2]), "=r"(f[3]) : "r"(addr));
}
__device__ __forceinline__ void ldm_x4t(uint32_t* f, uint32_t addr) {
    asm volatile("ldmatrix.sync.aligned.m8n8.x4.trans.shared.b16 {%0,%1,%2,%3}, [%4];"
                 : "=r"(f[0]), "=r"(f[1]), "=r"(f[2]), "=r"(f[3]) : "r"(addr));
}
__device__ __forceinline__ void mma_bf16(float* c, const uint32_t* a, const uint32_t* b) {
    asm volatile(
        "mma.sync.aligned.m16n8k16.row.col.f32.bf16.bf16.f32 "
        "{%0,%1,%2,%3}, {%4,%5,%6,%7}, {%8,%9}, {%0,%1,%2,%3};"
        : "+f"(c[0]), "+f"(c[1]), "+f"(c[2]), "+f"(c[3])
        : "r"(a[0]), "r"(a[1]), "r"(a[2]), "r"(a[3]), "r"(b[0]), "r"(b[1]));
}
__device__ __forceinline__ uint32_t pack_bf16(float x, float y) {
    __nv_bfloat16 hx = __float2bfloat16_rn(x);
    __nv_bfloat16 hy = __float2bfloat16_rn(y);
    return ((uint32_t)__bfloat16_as_ushort(hy) << 16) | __bfloat16_as_ushort(hx);
}
__device__ __forceinline__ float bf_res(float f) {
    return f - __bfloat162float(__float2bfloat16_rn(f));
}

// =============== W split (hi/lo bf16) + zero g_sumwh =======================
__global__ __launch_bounds__(256) void convw_kernel(const float* __restrict__ W) {
    if (blockIdx.x < 2) g_sumwh[blockIdx.x * 256 + threadIdx.x] = 0.0f;
    int i = blockIdx.x * 256 + threadIdx.x;
    float4 v = ((const float4*)W)[i];
    g_Whi[i * 2]     = pack_bf16(v.x, v.y);
    g_Whi[i * 2 + 1] = pack_bf16(v.z, v.w);
    g_Wlo[i * 2]     = pack_bf16(bf_res(v.x), bf_res(v.y));
    g_Wlo[i * 2 + 1] = pack_bf16(bf_res(v.z), bf_res(v.w));
}

// =============== CSR build: warp/row, 4 loads in flight ====================
__global__ void csr_build_kernel(const float* __restrict__ adj) {
    int warp = (blockIdx.x * blockDim.x + threadIdx.x) >> 5;
    int lane = threadIdx.x & 31;
    if (warp >= N_) return;
    const float4* row = (const float4*)(adj + (size_t)warp * N_);
    int cnt = 0;
    for (int base = 0; base < N_; base += 512) {
        float4 v0 = row[(base >> 2) + lane];
        float4 v1 = row[(base >> 2) + 32 + lane];
        float4 v2 = row[(base >> 2) + 64 + lane];
        float4 v3 = row[(base >> 2) + 96 + lane];
        float c16[16] = {v0.x, v0.y, v0.z, v0.w, v1.x, v1.y, v1.z, v1.w,
                         v2.x, v2.y, v2.z, v2.w, v3.x, v3.y, v3.z, v3.w};
#pragma unroll
        for (int h = 0; h < 4; h++) {
#pragma unroll
            for (int c = 0; c < 4; c++) {
                float f = c16[h * 4 + c];
                unsigned m = __ballot_sync(0xffffffffu, f > 0.0f);
                if (f > 0.0f) {
                    int pos = cnt + __popc(m & ((1u << lane) - 1u));
                    if (pos < MAXDEG)
                        g_cols[warp * MAXDEG + pos] = base + h * 128 + lane * 4 + c;
                }
                cnt += __popc(m);
            }
        }
    }
    if (lane == 0) g_deg[warp] = cnt < MAXDEG ? cnt : MAXDEG;
}

// ============ HMMA GEMM: wh = x @ W  (M=16384, N=128, K=512) ===============
#define KC 32
#define NCH (DIN_ / KC)
#define A_STG 16384
#define B_STG 16384
#define SM_A 0
#define SM_B (2 * A_STG)
#define SM_SD (SM_B + 2 * B_STG)
#define SM_AV (SM_SD + 1024)
#define SM_CS (SM_AV + 1024)
#define SMEM_TOTAL (SM_CS + 512)

__device__ __forceinline__ uint32_t a_off(int r, int gran) {
    return (uint32_t)(r * 128 + ((gran ^ (r & 7)) << 4));
}
__device__ __forceinline__ uint32_t b_off2(int k, int gran) {
    return (uint32_t)(k * 256 + ((gran ^ (k & 7)) << 4));
}

__global__ __launch_bounds__(256, 1) void gemm_hmma_kernel(
    const float* __restrict__ x, const float* __restrict__ a) {
    extern __shared__ char smem[];
    const uint32_t sb = smem_u32(smem);
    const int tid = threadIdx.x;
    const int wid = tid >> 5, lane = tid & 31;
    const int wm = wid >> 1, wn = wid & 1;
    const int tig = lane & 3, grp = lane >> 2;

    float* s_sm = (float*)(smem + SM_SD);
    float* d_sm = (float*)(smem + SM_SD + 512);
    float* a_s  = (float*)(smem + SM_AV);
    float* a_d  = (float*)(smem + SM_AV + 512);
    float* cs   = (float*)(smem + SM_CS);
    if (tid < 128) {
        s_sm[tid] = 0.0f; d_sm[tid] = 0.0f; cs[tid] = 0.0f;
        a_s[tid] = a[tid]; a_d[tid] = a[DOUT_ + tid];
    }

    const int R0 = blockIdx.x * 128;
    const int arow = tid >> 1, akoff = (tid & 1) * 16;
    const float* pA = x + (size_t)(R0 + arow) * DIN_ + akoff;
    const int bk = tid >> 3, bgr = (tid & 7) * 2;
    const uint4* Whi4 = (const uint4*)g_Whi;
    const uint4* Wlo4 = (const uint4*)g_Wlo;

    float acc[2][8][4];
#pragma unroll
    for (int i = 0; i < 2; i++)
#pragma unroll
        for (int j = 0; j < 8; j++)
#pragma unroll
            for (int q = 0; q < 4; q++) acc[i][j][q] = 0.0f;

    float4 ra[4];
    uint4 rbh[2], rbl[2];
#pragma unroll
    for (int i = 0; i < 4; i++) ra[i] = *(const float4*)(pA + i * 4);
    {
        int gi = bk * 16 + bgr;
        rbh[0] = Whi4[gi];     rbh[1] = Whi4[gi + 1];
        rbl[0] = Wlo4[gi];     rbl[1] = Wlo4[gi + 1];
    }

    for (int c = 0; c < NCH; c++) {
        const int buf = c & 1;
        char* Abuf = smem + SM_A + buf * A_STG;
        char* Bhi  = smem + SM_B + buf * B_STG;
        char* Blo  = Bhi + 8192;

        {
            const float* fa = (const float*)ra;
#pragma unroll
            for (int p = 0; p < 8; p++) {
                float f0 = fa[2 * p], f1 = fa[2 * p + 1];
                uint32_t hv = pack_bf16(f0, f1);
                uint32_t lv = pack_bf16(bf_res(f0), bf_res(f1));
                int kl = akoff + 2 * p;
                int gr = kl >> 3, wi = (kl & 7) * 2;
                *(uint32_t*)(Abuf + a_off(arow, gr) + wi)     = hv;
                *(uint32_t*)(Abuf + a_off(arow, gr + 4) + wi) = lv;
            }
            *(uint4*)(Bhi + b_off2(bk, bgr))     = rbh[0];
            *(uint4*)(Bhi + b_off2(bk, bgr + 1)) = rbh[1];
            *(uint4*)(Blo + b_off2(bk, bgr))     = rbl[0];
            *(uint4*)(Blo + b_off2(bk, bgr + 1)) = rbl[1];
        }
        __syncthreads();

        if (c + 1 < NCH) {
            const float* qA = pA + (c + 1) * KC;
#pragma unroll
            for (int i = 0; i < 4; i++) ra[i] = *(const float4*)(qA + i * 4);
            int gi = (c + 1) * 512 + bk * 16 + bgr;
            rbh[0] = Whi4[gi];     rbh[1] = Whi4[gi + 1];
            rbl[0] = Wlo4[gi];     rbl[1] = Wlo4[gi + 1];
        }

        const uint32_t Abase = sb + SM_A + buf * A_STG;
        const uint32_t BhiB  = sb + SM_B + buf * B_STG;
        const uint32_t BloB  = BhiB + 8192;
#pragma unroll
        for (int ks = 0; ks < 2; ks++) {
            uint32_t ahi[2][4], alo[2][4];
#pragma unroll
            for (int mt = 0; mt < 2; mt++) {
                int R = wm * 32 + mt * 16 + (lane & 15);
                int gh = 2 * ks + (lane >> 4);
                ldm_x4(ahi[mt], Abase + a_off(R, gh));
                ldm_x4(alo[mt], Abase + a_off(R, gh + 4));
            }
            int kk = 16 * ks + (lane & 15);
#pragma unroll
            for (int ntp = 0; ntp < 4; ntp++) {
                int gn = wn * 8 + ntp * 2 + (lane >> 4);
                uint32_t bhi[4], blo[4];
                ldm_x4t(bhi, BhiB + b_off2(kk, gn));
                ldm_x4t(blo, BloB + b_off2(kk, gn));
#pragma unroll
                for (int mt = 0; mt < 2; mt++) {
                    mma_bf16(acc[mt][ntp * 2],     ahi[mt], bhi);
                    mma_bf16(acc[mt][ntp * 2 + 1], ahi[mt], bhi + 2);
                    mma_bf16(acc[mt][ntp * 2],     ahi[mt], blo);
                    mma_bf16(acc[mt][ntp * 2 + 1], ahi[mt], blo + 2);
                    mma_bf16(acc[mt][ntp * 2],     alo[mt], bhi);
                    mma_bf16(acc[mt][ntp * 2 + 1], alo[mt], bhi + 2);
                }
            }
        }
        __syncthreads();
    }

    // ---- epilogue: store wh (fp16), fused s/d dots + column sums ----
    float sacc[2][2] = {{0, 0}, {0, 0}}, dacc[2][2] = {{0, 0}, {0, 0}};
#pragma unroll
    for (int mt = 0; mt < 2; mt++) {
        int rbase = R0 + wm * 32 + mt * 16 + grp;
#pragma unroll
        for (int nt = 0; nt < 8; nt++) {
            int col = wn * 64 + nt * 8 + tig * 2;
            float* cf = acc[mt][nt];
            sacc[mt][0] += cf[0] * a_s[col] + cf[1] * a_s[col + 1];
            sacc[mt][1] += cf[2] * a_s[col] + cf[3] * a_s[col + 1];
            dacc[mt][0] += cf[0] * a_d[col] + cf[1] * a_d[col + 1];
            dacc[mt][1] += cf[2] * a_d[col] + cf[3] * a_d[col + 1];
            *(__half2*)&g_whh[(size_t)rbase * DOUT_ + col] =
                __float22half2_rn(make_float2(cf[0], cf[1]));
            *(__half2*)&g_whh[(size_t)(rbase + 8) * DOUT_ + col] =
                __float22half2_rn(make_float2(cf[2], cf[3]));

            float v0 = cf[0] + cf[2];
            float v1 = cf[1] + cf[3];
#pragma unroll
            for (int off = 16; off >= 4; off >>= 1) {
                v0 += __shfl_down_sync(0xffffffffu, v0, off);
                v1 += __shfl_down_sync(0xffffffffu, v1, off);
            }
            if (lane < 4) {
                atomicAdd(&cs[col], v0);
                atomicAdd(&cs[col + 1], v1);
            }
        }
    }
#pragma unroll
    for (int mt = 0; mt < 2; mt++)
#pragma unroll
        for (int h = 0; h < 2; h++) {
            sacc[mt][h] += __shfl_xor_sync(0xffffffffu, sacc[mt][h], 1);
            sacc[mt][h] += __shfl_xor_sync(0xffffffffu, sacc[mt][h], 2);
            dacc[mt][h] += __shfl_xor_sync(0xffffffffu, dacc[mt][h], 1);
            dacc[mt][h] += __shfl_xor_sync(0xffffffffu, dacc[mt][h], 2);
        }
    if (tig == 0) {
#pragma unroll
        for (int mt = 0; mt < 2; mt++) {
            int r = wm * 32 + mt * 16 + grp;
            atomicAdd(&s_sm[r], sacc[mt][0]);
            atomicAdd(&s_sm[r + 8], sacc[mt][1]);
            atomicAdd(&d_sm[r], dacc[mt][0]);
            atomicAdd(&d_sm[r + 8], dacc[mt][1]);
        }
    }
    __syncthreads();
    if (tid < 128) {
        int b = R0 / N_;
        int il = (R0 % N_) + tid;          // row within graph
        g_sT[il * 4 + b] = s_sm[tid];      // transposed layout [i][b]
        g_dT[il * 4 + b] = d_sm[tid];
        atomicAdd(&g_sumwh[b * DOUT_ + tid], cs[tid]);
    }
}

// ========== attention SpMM: warp per row, ALL 4 graphs fused ================
__global__ __launch_bounds__(256) void attn_kernel() {
    __shared__ float sh_e[8][MAXDEG][4];   // 32 KB
    __shared__ int   sh_j[8][MAXDEG];      //  8 KB
    int i = (blockIdx.x * blockDim.x + threadIdx.x) >> 5;
    int lane = threadIdx.x & 31;
    int w = threadIdx.x >> 5;
    if (i >= N_) return;
    int deg = g_deg[i];

    if (deg == 0) {
        float inv = 1.0f / (float)N_;
#pragma unroll
        for (int b = 0; b < 4; b++) {
            float4 m = ((const float4*)&g_sumwh[b * DOUT_])[lane];
            uint2 o;
            *(__half2*)&o.x = __float22half2_rn(make_float2(m.x * inv, m.y * inv));
            *(__half2*)&o.y = __float22half2_rn(make_float2(m.z * inv, m.w * inv));
            ((uint2*)&g_outh[((size_t)b * N_ + i) * DOUT_])[lane] = o;
        }
        return;
    }

    float4 s4 = *(const float4*)&g_sT[i * 4];
    float mx0 = NEG_BIG, mx1 = NEG_BIG, mx2 = NEG_BIG, mx3 = NEG_BIG;
    for (int t = lane; t < deg; t += 32) {
        int j = g_cols[i * MAXDEG + t];
        sh_j[w][t] = j;
        float4 d4 = *(const float4*)&g_dT[j * 4];
        float e0 = s4.x + d4.x; e0 = e0 > 0.f ? e0 : 0.01f * e0;
        float e1 = s4.y + d4.y; e1 = e1 > 0.f ? e1 : 0.01f * e1;
        float e2 = s4.z + d4.z; e2 = e2 > 0.f ? e2 : 0.01f * e2;
        float e3 = s4.w + d4.w; e3 = e3 > 0.f ? e3 : 0.01f * e3;
        *(float4*)sh_e[w][t] = make_float4(e0, e1, e2, e3);
        mx0 = fmaxf(mx0, e0); mx1 = fmaxf(mx1, e1);
        mx2 = fmaxf(mx2, e2); mx3 = fmaxf(mx3, e3);
    }
#pragma unroll
    for (int off = 16; off > 0; off >>= 1) {
        mx0 = fmaxf(mx0, __shfl_xor_sync(0xffffffffu, mx0, off));
        mx1 = fmaxf(mx1, __shfl_xor_sync(0xffffffffu, mx1, off));
        mx2 = fmaxf(mx2, __shfl_xor_sync(0xffffffffu, mx2, off));
        mx3 = fmaxf(mx3, __shfl_xor_sync(0xffffffffu, mx3, off));
    }
    __syncwarp();

    float se0 = 0.f, se1 = 0.f, se2 = 0.f, se3 = 0.f;
    for (int t = lane; t < deg; t += 32) {
        float4 e = *(float4*)sh_e[w][t];
        float p0 = __expf(e.x - mx0), p1 = __expf(e.y - mx1);
        float p2 = __expf(e.z - mx2), p3 = __expf(e.w - mx3);
        *(float4*)sh_e[w][t] = make_float4(p0, p1, p2, p3);
        se0 += p0; se1 += p1; se2 += p2; se3 += p3;
    }
#pragma unroll
    for (int off = 16; off > 0; off >>= 1) {
        se0 += __shfl_xor_sync(0xffffffffu, se0, off);
        se1 += __shfl_xor_sync(0xffffffffu, se1, off);
        se2 += __shfl_xor_sync(0xffffffffu, se2, off);
        se3 += __shfl_xor_sync(0xffffffffu, se3, off);
    }
    float iv0 = 1.f / se0, iv1 = 1.f / se1, iv2 = 1.f / se2, iv3 = 1.f / se3;
    __syncwarp();

    const uint2* wh0 = (const uint2*)g_whh;
    const uint2* wh1 = wh0 + (size_t)N_ * 32;
    const uint2* wh2 = wh1 + (size_t)N_ * 32;
    const uint2* wh3 = wh2 + (size_t)N_ * 32;
    float ac[4][4];
#pragma unroll
    for (int b = 0; b < 4; b++)
#pragma unroll
        for (int q = 0; q < 4; q++) ac[b][q] = 0.f;

    int k = 0;
    for (; k + 2 <= deg; k += 2) {
        int j0 = sh_j[w][k], j1 = sh_j[w][k + 1];
        size_t o0 = (size_t)j0 * 32 + lane, o1 = (size_t)j1 * 32 + lane;
        uint2 v[8];
        v[0] = wh0[o0]; v[1] = wh1[o0]; v[2] = wh2[o0]; v[3] = wh3[o0];
        v[4] = wh0[o1]; v[5] = wh1[o1]; v[6] = wh2[o1]; v[7] = wh3[o1];
        float4 p0 = *(float4*)sh_e[w][k];
        float4 p1 = *(float4*)sh_e[w][k + 1];
        float pw[8] = {p0.x * iv0, p0.y * iv1, p0.z * iv2, p0.w * iv3,
                       p1.x * iv0, p1.y * iv1, p1.z * iv2, p1.w * iv3};
#pragma unroll
        for (int u = 0; u < 8; u++) {
            float2 f0 = __half22float2(*(__half2*)&v[u].x);
            float2 f1 = __half22float2(*(__half2*)&v[u].y);
            int b = u & 3;
            ac[b][0] += pw[u] * f0.x; ac[b][1] += pw[u] * f0.y;
            ac[b][2] += pw[u] * f1.x; ac[b][3] += pw[u] * f1.y;
        }
    }
    if (k < deg) {
        int j0 = sh_j[w][k];
        size_t o0 = (size_t)j0 * 32 + lane;
        uint2 v[4] = {wh0[o0], wh1[o0], wh2[o0], wh3[o0]};
        float4 p0 = *(float4*)sh_e[w][k];
        float pw[4] = {p0.x * iv0, p0.y * iv1, p0.z * iv2, p0.w * iv3};
#pragma unroll
        for (int b = 0; b < 4; b++) {
            float2 f0 = __half22float2(*(__half2*)&v[b].x);
            float2 f1 = __half22float2(*(__half2*)&v[b].y);
            ac[b][0] += pw[b] * f0.x; ac[b][1] += pw[b] * f0.y;
            ac[b][2] += pw[b] * f1.x; ac[b][3] += pw[b] * f1.y;
        }
    }
#pragma unroll
    for (int b = 0; b < 4; b++) {
        uint2 o;
        *(__half2*)&o.x = __float22half2_rn(make_float2(ac[b][0], ac[b][1]));
        *(__half2*)&o.y = __float22half2_rn(make_float2(ac[b][2], ac[b][3]));
        ((uint2*)&g_outh[((size_t)b * N_ + i) * DOUT_])[lane] = o;
    }
}

// ========== final: y = relu(adj @ out), warp per row, 4 graphs fused ========
__global__ __launch_bounds__(256) void final_kernel(float* __restrict__ y) {
    int i = (blockIdx.x * blockDim.x + threadIdx.x) >> 5;
    int lane = threadIdx.x & 31;
    if (i >= N_) return;
    int deg = g_deg[i];

    const uint2* ou0 = (const uint2*)g_outh;
    const uint2* ou1 = ou0 + (size_t)N_ * 32;
    const uint2* ou2 = ou1 + (size_t)N_ * 32;
    const uint2* ou3 = ou2 + (size_t)N_ * 32;
    float ac[4][4];
#pragma unroll
    for (int b = 0; b < 4; b++)
#pragma unroll
        for (int q = 0; q < 4; q++) ac[b][q] = 0.f;

    int k = 0;
    for (; k + 2 <= deg; k += 2) {
        int j0 = g_cols[i * MAXDEG + k], j1 = g_cols[i * MAXDEG + k + 1];
        size_t o0 = (size_t)j0 * 32 + lane, o1 = (size_t)j1 * 32 + lane;
        uint2 v[8];
        v[0] = ou0[o0]; v[1] = ou1[o0]; v[2] = ou2[o0]; v[3] = ou3[o0];
        v[4] = ou0[o1]; v[5] = ou1[o1]; v[6] = ou2[o1]; v[7] = ou3[o1];
#pragma unroll
        for (int u = 0; u < 8; u++) {
            float2 f0 = __half22float2(*(__half2*)&v[u].x);
            float2 f1 = __half22float2(*(__half2*)&v[u].y);
            int b = u & 3;
            ac[b][0] += f0.x; ac[b][1] += f0.y; ac[b][2] += f1.x; ac[b][3] += f1.y;
        }
    }
    if (k < deg) {
        size_t o0 = (size_t)g_cols[i * MAXDEG + k] * 32 + lane;
        uint2 v[4] = {ou0[o0], ou1[o0], ou2[o0], ou3[o0]};
#pragma unroll
        for (int b = 0; b < 4; b++) {
            float2 f0 = __half22float2(*(__half2*)&v[b].x);
            float2 f1 = __half22float2(*(__half2*)&v[b].y);
            ac[b][0] += f0.x; ac[b][1] += f0.y; ac[b][2] += f1.x; ac[b][3] += f1.y;
        }
    }
#pragma unroll
    for (int b = 0; b < 4; b++) {
        float4 r = make_float4(fmaxf(ac[b][0], 0.f), fmaxf(ac[b][1], 0.f),
                               fmaxf(ac[b][2], 0.f), fmaxf(ac[b][3], 0.f));
        ((float4*)&y[((size_t)b * N_ + i) * DOUT_])[lane] = r;
    }
}

// ---------------- launch ----------------
extern "C" void kernel_launch(void* const* d_in, const int* in_sizes, int n_in,
                              void* d_out, int out_size) {
    const float* x   = (const float*)d_in[0];  // (B, N, DIN)
    const float* adj = (const float*)d_in[1];  // (N, N)
    const float* wts = (const float*)d_in[2];  // (DIN, DOUT)
    const float* a   = (const float*)d_in[3];  // (2*DOUT, 1)
    float* y = (float*)d_out;

    static cudaStream_t s2;
    static cudaEvent_t evA, evC;
    static int inited = 0;
    if (!inited) {
        cudaFuncSetAttribute(gemm_hmma_kernel,
                             cudaFuncAttributeMaxDynamicSharedMemorySize, SMEM_TOTAL);
        cudaStreamCreateWithFlags(&s2, cudaStreamNonBlocking);
        cudaEventCreateWithFlags(&evA, cudaEventDisableTiming);
        cudaEventCreateWithFlags(&evC, cudaEventDisableTiming);
        inited = 1;
    }
    cudaStream_t s0 = 0;

    // fork: csr on s2 overlaps convW+GEMM on s0; join before attn
    cudaEventRecord(evA, s0);
    cudaStreamWaitEvent(s2, evA, 0);
    csr_build_kernel<<<N_ / 8, 256, 0, s2>>>(adj);
    cudaEventRecord(evC, s2);

    convw_kernel<<<DIN_ * DOUT_ / 1024, 256, 0, s0>>>(wts);
    gemm_hmma_kernel<<<(B_ * N_) / 128, 256, SMEM_TOTAL, s0>>>(x, a);
    cudaStreamWaitEvent(s0, evC, 0);

    attn_kernel<<<N_ / 8, 256, 0, s0>>>();
    final_kernel<<<N_ / 8, 256, 0, s0>>>(y);
}

// round 10
// speedup vs baseline: 1.3008x; 1.0308x over previous
#include <cuda_runtime.h>
#include <cuda_bf16.h>
#include <cuda_fp16.h>
#include <math.h>
#include <stdint.h>

#define B_    4
#define N_    4096
#define DIN_  512
#define DOUT_ 128
#define MAXDEG 128
#define NEG_BIG -1e30f

// ---------------- scratch (static device memory; no allocs) ----------------
__device__ __half g_whh[B_ * N_ * DOUT_];   // x @ W (fp16)   4 MB
__device__ __half g_outh[B_ * N_ * DOUT_];  // att @ wh       4 MB
__device__ float g_sT[N_ * 4];              // s transposed [i][b]
__device__ float g_dT[N_ * 4];              // d transposed [i][b]
__device__ float g_sumwh[B_ * DOUT_];       // per-graph colsum (deg==0 fallback)
__device__ int   g_cols[N_ * MAXDEG];
__device__ int   g_deg[N_];
__device__ uint32_t g_Wh[DIN_ * DOUT_ / 2]; // W as fp16x2 packed (128 KB)

// ============================ helpers =======================================
__device__ __forceinline__ uint32_t smem_u32(const void* p) {
    uint32_t a;
    asm("{ .reg .u64 t; cvta.to.shared.u64 t, %1; cvt.u32.u64 %0, t; }" : "=r"(a) : "l"(p));
    return a;
}
__device__ __forceinline__ void ldm_x4(uint32_t* f, uint32_t addr) {
    asm volatile("ldmatrix.sync.aligned.m8n8.x4.shared.b16 {%0,%1,%2,%3}, [%4];"
                 : "=r"(f[0]), "=r"(f[1]), "=r"(f[2]), "=r"(f[3]) : "r"(addr));
}
__device__ __forceinline__ void ldm_x4t(uint32_t* f, uint32_t addr) {
    asm volatile("ldmatrix.sync.aligned.m8n8.x4.trans.shared.b16 {%0,%1,%2,%3}, [%4];"
                 : "=r"(f[0]), "=r"(f[1]), "=r"(f[2]), "=r"(f[3]) : "r"(addr));
}
__device__ __forceinline__ void mma_f16(float* c, const uint32_t* a, const uint32_t* b) {
    asm volatile(
        "mma.sync.aligned.m16n8k16.row.col.f32.f16.f16.f32 "
        "{%0,%1,%2,%3}, {%4,%5,%6,%7}, {%8,%9}, {%0,%1,%2,%3};"
        : "+f"(c[0]), "+f"(c[1]), "+f"(c[2]), "+f"(c[3])
        : "r"(a[0]), "r"(a[1]), "r"(a[2]), "r"(a[3]), "r"(b[0]), "r"(b[1]));
}
__device__ __forceinline__ uint32_t pack_half(float x, float y) {
    __half2 h = __floats2half2_rn(x, y);
    return *(uint32_t*)&h;
}
__device__ __forceinline__ float h_res(float f) {
    return f - __half2float(__float2half_rn(f));
}

// =============== W -> fp16 + zero g_sumwh ==================================
__global__ __launch_bounds__(256) void convw_kernel(const float* __restrict__ W) {
    if (blockIdx.x < 2) g_sumwh[blockIdx.x * 256 + threadIdx.x] = 0.0f;
    int i = blockIdx.x * 256 + threadIdx.x;     // 16384 float4s
    float4 v = ((const float4*)W)[i];
    g_Wh[i * 2]     = pack_half(v.x, v.y);
    g_Wh[i * 2 + 1] = pack_half(v.z, v.w);
}

// =============== CSR build: warp/row, 4 loads in flight ====================
__global__ void csr_build_kernel(const float* __restrict__ adj) {
    int warp = (blockIdx.x * blockDim.x + threadIdx.x) >> 5;
    int lane = threadIdx.x & 31;
    if (warp >= N_) return;
    const float4* row = (const float4*)(adj + (size_t)warp * N_);
    int cnt = 0;
    for (int base = 0; base < N_; base += 512) {
        float4 v0 = row[(base >> 2) + lane];
        float4 v1 = row[(base >> 2) + 32 + lane];
        float4 v2 = row[(base >> 2) + 64 + lane];
        float4 v3 = row[(base >> 2) + 96 + lane];
        float c16[16] = {v0.x, v0.y, v0.z, v0.w, v1.x, v1.y, v1.z, v1.w,
                         v2.x, v2.y, v2.z, v2.w, v3.x, v3.y, v3.z, v3.w};
#pragma unroll
        for (int h = 0; h < 4; h++) {
#pragma unroll
            for (int c = 0; c < 4; c++) {
                float f = c16[h * 4 + c];
                unsigned m = __ballot_sync(0xffffffffu, f > 0.0f);
                if (f > 0.0f) {
                    int pos = cnt + __popc(m & ((1u << lane) - 1u));
                    if (pos < MAXDEG)
                        g_cols[warp * MAXDEG + pos] = base + h * 128 + lane * 4 + c;
                }
                cnt += __popc(m);
            }
        }
    }
    if (lane == 0) g_deg[warp] = cnt < MAXDEG ? cnt : MAXDEG;
}

// ===== HMMA GEMM (fp16, A split hi/lo, W single): wh = x @ W ===============
#define KC 32
#define NCH (DIN_ / KC)
#define A_STG 16384              // 128 rows * (32k hi + 32k lo) * 2B
#define B_STG 8192               // 32 k * 128 n * 2B
#define SM_A 0
#define SM_B (2 * A_STG)
#define SM_SD (SM_B + 2 * B_STG)
#define SM_AV (SM_SD + 1024)
#define SM_CS (SM_AV + 1024)
#define SMEM_TOTAL (SM_CS + 512)

__device__ __forceinline__ uint32_t a_off(int r, int gran) {
    return (uint32_t)(r * 128 + ((gran ^ (r & 7)) << 4));
}
__device__ __forceinline__ uint32_t b_off2(int k, int gran) {
    return (uint32_t)(k * 256 + ((gran ^ (k & 7)) << 4));
}

__global__ __launch_bounds__(256, 1) void gemm_hmma_kernel(
    const float* __restrict__ x, const float* __restrict__ a) {
    extern __shared__ char smem[];
    const uint32_t sb = smem_u32(smem);
    const int tid = threadIdx.x;
    const int wid = tid >> 5, lane = tid & 31;
    const int wm = wid >> 1, wn = wid & 1;
    const int tig = lane & 3, grp = lane >> 2;

    float* s_sm = (float*)(smem + SM_SD);
    float* d_sm = (float*)(smem + SM_SD + 512);
    float* a_s  = (float*)(smem + SM_AV);
    float* a_d  = (float*)(smem + SM_AV + 512);
    float* cs   = (float*)(smem + SM_CS);
    if (tid < 128) {
        s_sm[tid] = 0.0f; d_sm[tid] = 0.0f; cs[tid] = 0.0f;
        a_s[tid] = a[tid]; a_d[tid] = a[DOUT_ + tid];
    }

    const int R0 = blockIdx.x * 128;
    const int arow = tid >> 1, akoff = (tid & 1) * 16;
    const float* pA = x + (size_t)(R0 + arow) * DIN_ + akoff;
    const int bk = tid >> 3, bgr = (tid & 7) * 2;
    const uint4* Wh4 = (const uint4*)g_Wh;

    float acc[2][8][4];
#pragma unroll
    for (int i = 0; i < 2; i++)
#pragma unroll
        for (int j = 0; j < 8; j++)
#pragma unroll
            for (int q = 0; q < 4; q++) acc[i][j][q] = 0.0f;

    float4 ra[4];
    uint4 rbh[2];
#pragma unroll
    for (int i = 0; i < 4; i++) ra[i] = *(const float4*)(pA + i * 4);
    {
        int gi = bk * 16 + bgr;
        rbh[0] = Wh4[gi];  rbh[1] = Wh4[gi + 1];
    }

    for (int c = 0; c < NCH; c++) {
        const int buf = c & 1;
        char* Abuf = smem + SM_A + buf * A_STG;
        char* Bbuf = smem + SM_B + buf * B_STG;

        {
            const float* fa = (const float*)ra;
#pragma unroll
            for (int p = 0; p < 8; p++) {
                float f0 = fa[2 * p], f1 = fa[2 * p + 1];
                uint32_t hv = pack_half(f0, f1);
                uint32_t lv = pack_half(h_res(f0), h_res(f1));
                int kl = akoff + 2 * p;
                int gr = kl >> 3, wi = (kl & 7) * 2;
                *(uint32_t*)(Abuf + a_off(arow, gr) + wi)     = hv;
                *(uint32_t*)(Abuf + a_off(arow, gr + 4) + wi) = lv;
            }
            *(uint4*)(Bbuf + b_off2(bk, bgr))     = rbh[0];
            *(uint4*)(Bbuf + b_off2(bk, bgr + 1)) = rbh[1];
        }
        __syncthreads();

        if (c + 1 < NCH) {
            const float* qA = pA + (c + 1) * KC;
#pragma unroll
            for (int i = 0; i < 4; i++) ra[i] = *(const float4*)(qA + i * 4);
            int gi = (c + 1) * 512 + bk * 16 + bgr;
            rbh[0] = Wh4[gi];  rbh[1] = Wh4[gi + 1];
        }

        const uint32_t Abase = sb + SM_A + buf * A_STG;
        const uint32_t Bbase = sb + SM_B + buf * B_STG;
#pragma unroll
        for (int ks = 0; ks < 2; ks++) {
            uint32_t ahi[2][4], alo[2][4];
#pragma unroll
            for (int mt = 0; mt < 2; mt++) {
                int R = wm * 32 + mt * 16 + (lane & 15);
                int gh = 2 * ks + (lane >> 4);
                ldm_x4(ahi[mt], Abase + a_off(R, gh));
                ldm_x4(alo[mt], Abase + a_off(R, gh + 4));
            }
            int kk = 16 * ks + (lane & 15);
#pragma unroll
            for (int ntp = 0; ntp < 4; ntp++) {
                int gn = wn * 8 + ntp * 2 + (lane >> 4);
                uint32_t bb[4];
                ldm_x4t(bb, Bbase + b_off2(kk, gn));
#pragma unroll
                for (int mt = 0; mt < 2; mt++) {
                    mma_f16(acc[mt][ntp * 2],     ahi[mt], bb);
                    mma_f16(acc[mt][ntp * 2 + 1], ahi[mt], bb + 2);
                    mma_f16(acc[mt][ntp * 2],     alo[mt], bb);
                    mma_f16(acc[mt][ntp * 2 + 1], alo[mt], bb + 2);
                }
            }
        }
        __syncthreads();
    }

    // ---- epilogue: store wh (fp16), fused s/d dots + column sums ----
    float sacc[2][2] = {{0, 0}, {0, 0}}, dacc[2][2] = {{0, 0}, {0, 0}};
#pragma unroll
    for (int mt = 0; mt < 2; mt++) {
        int rbase = R0 + wm * 32 + mt * 16 + grp;
#pragma unroll
        for (int nt = 0; nt < 8; nt++) {
            int col = wn * 64 + nt * 8 + tig * 2;
            float* cf = acc[mt][nt];
            sacc[mt][0] += cf[0] * a_s[col] + cf[1] * a_s[col + 1];
            sacc[mt][1] += cf[2] * a_s[col] + cf[3] * a_s[col + 1];
            dacc[mt][0] += cf[0] * a_d[col] + cf[1] * a_d[col + 1];
            dacc[mt][1] += cf[2] * a_d[col] + cf[3] * a_d[col + 1];
            *(__half2*)&g_whh[(size_t)rbase * DOUT_ + col] =
                __float22half2_rn(make_float2(cf[0], cf[1]));
            *(__half2*)&g_whh[(size_t)(rbase + 8) * DOUT_ + col] =
                __float22half2_rn(make_float2(cf[2], cf[3]));

            float v0 = cf[0] + cf[2];
            float v1 = cf[1] + cf[3];
#pragma unroll
            for (int off = 16; off >= 4; off >>= 1) {
                v0 += __shfl_down_sync(0xffffffffu, v0, off);
                v1 += __shfl_down_sync(0xffffffffu, v1, off);
            }
            if (lane < 4) {
                atomicAdd(&cs[col], v0);
                atomicAdd(&cs[col + 1], v1);
            }
        }
    }
#pragma unroll
    for (int mt = 0; mt < 2; mt++)
#pragma unroll
        for (int h = 0; h < 2; h++) {
            sacc[mt][h] += __shfl_xor_sync(0xffffffffu, sacc[mt][h], 1);
            sacc[mt][h] += __shfl_xor_sync(0xffffffffu, sacc[mt][h], 2);
            dacc[mt][h] += __shfl_xor_sync(0xffffffffu, dacc[mt][h], 1);
            dacc[mt][h] += __shfl_xor_sync(0xffffffffu, dacc[mt][h], 2);
        }
    if (tig == 0) {
#pragma unroll
        for (int mt = 0; mt < 2; mt++) {
            int r = wm * 32 + mt * 16 + grp;
            atomicAdd(&s_sm[r], sacc[mt][0]);
            atomicAdd(&s_sm[r + 8], sacc[mt][1]);
            atomicAdd(&d_sm[r], dacc[mt][0]);
            atomicAdd(&d_sm[r + 8], dacc[mt][1]);
        }
    }
    __syncthreads();
    if (tid < 128) {
        int b = R0 / N_;
        int il = (R0 % N_) + tid;
        g_sT[il * 4 + b] = s_sm[tid];
        g_dT[il * 4 + b] = d_sm[tid];
        atomicAdd(&g_sumwh[b * DOUT_ + tid], cs[tid]);
    }
}

// ==== attention SpMM: warp per (row, 64-col half), 4 graphs fused ==========
// Edge scratch is PER-WARP (indexed by w, not row) — no cross-warp sharing.
__global__ __launch_bounds__(256) void attn_kernel() {
    __shared__ float sh_e[8][MAXDEG][4];   // 16 KB
    __shared__ int   sh_j[8][MAXDEG];      //  4 KB
    int lane = threadIdx.x & 31;
    int w = threadIdx.x >> 5;
    int rl = w >> 1, half = w & 1;
    int i = blockIdx.x * 4 + rl;
    int deg = g_deg[i];
    int co = (half << 5) + lane;           // uint index within row (64 uints)

    if (deg == 0) {
        float inv = 1.0f / (float)N_;
#pragma unroll
        for (int b = 0; b < 4; b++) {
            float2 m = ((const float2*)&g_sumwh[b * DOUT_])[co];
            ((uint32_t*)&g_outh[((size_t)b * N_ + i) * DOUT_])[co] =
                pack_half(m.x * inv, m.y * inv);
        }
        return;
    }

    float4 s4 = *(const float4*)&g_sT[i * 4];
    float mx0 = NEG_BIG, mx1 = NEG_BIG, mx2 = NEG_BIG, mx3 = NEG_BIG;
    for (int t = lane; t < deg; t += 32) {
        int j = g_cols[i * MAXDEG + t];
        sh_j[w][t] = j;
        float4 d4 = *(const float4*)&g_dT[j * 4];
        float e0 = s4.x + d4.x; e0 = e0 > 0.f ? e0 : 0.01f * e0;
        float e1 = s4.y + d4.y; e1 = e1 > 0.f ? e1 : 0.01f * e1;
        float e2 = s4.z + d4.z; e2 = e2 > 0.f ? e2 : 0.01f * e2;
        float e3 = s4.w + d4.w; e3 = e3 > 0.f ? e3 : 0.01f * e3;
        *(float4*)sh_e[w][t] = make_float4(e0, e1, e2, e3);
        mx0 = fmaxf(mx0, e0); mx1 = fmaxf(mx1, e1);
        mx2 = fmaxf(mx2, e2); mx3 = fmaxf(mx3, e3);
    }
#pragma unroll
    for (int off = 16; off > 0; off >>= 1) {
        mx0 = fmaxf(mx0, __shfl_xor_sync(0xffffffffu, mx0, off));
        mx1 = fmaxf(mx1, __shfl_xor_sync(0xffffffffu, mx1, off));
        mx2 = fmaxf(mx2, __shfl_xor_sync(0xffffffffu, mx2, off));
        mx3 = fmaxf(mx3, __shfl_xor_sync(0xffffffffu, mx3, off));
    }
    __syncwarp();

    float se0 = 0.f, se1 = 0.f, se2 = 0.f, se3 = 0.f;
    for (int t = lane; t < deg; t += 32) {
        float4 e = *(float4*)sh_e[w][t];
        float p0 = __expf(e.x - mx0), p1 = __expf(e.y - mx1);
        float p2 = __expf(e.z - mx2), p3 = __expf(e.w - mx3);
        *(float4*)sh_e[w][t] = make_float4(p0, p1, p2, p3);
        se0 += p0; se1 += p1; se2 += p2; se3 += p3;
    }
#pragma unroll
    for (int off = 16; off > 0; off >>= 1) {
        se0 += __shfl_xor_sync(0xffffffffu, se0, off);
        se1 += __shfl_xor_sync(0xffffffffu, se1, off);
        se2 += __shfl_xor_sync(0xffffffffu, se2, off);
        se3 += __shfl_xor_sync(0xffffffffu, se3, off);
    }
    float iv0 = 1.f / se0, iv1 = 1.f / se1, iv2 = 1.f / se2, iv3 = 1.f / se3;
    __syncwarp();

    const uint32_t* wh0 = (const uint32_t*)g_whh;
    const uint32_t* wh1 = wh0 + (size_t)N_ * 64;
    const uint32_t* wh2 = wh1 + (size_t)N_ * 64;
    const uint32_t* wh3 = wh2 + (size_t)N_ * 64;
    float ac[4][2];
#pragma unroll
    for (int b = 0; b < 4; b++) { ac[b][0] = 0.f; ac[b][1] = 0.f; }

    int k = 0;
    for (; k + 2 <= deg; k += 2) {
        int j0 = sh_j[w][k], j1 = sh_j[w][k + 1];
        size_t o0 = (size_t)j0 * 64 + co, o1 = (size_t)j1 * 64 + co;
        uint32_t v[8];
        v[0] = wh0[o0]; v[1] = wh1[o0]; v[2] = wh2[o0]; v[3] = wh3[o0];
        v[4] = wh0[o1]; v[5] = wh1[o1]; v[6] = wh2[o1]; v[7] = wh3[o1];
        float4 p0 = *(float4*)sh_e[w][k];
        float4 p1 = *(float4*)sh_e[w][k + 1];
        float pw[8] = {p0.x * iv0, p0.y * iv1, p0.z * iv2, p0.w * iv3,
                       p1.x * iv0, p1.y * iv1, p1.z * iv2, p1.w * iv3};
#pragma unroll
        for (int u = 0; u < 8; u++) {
            float2 f = __half22float2(*(__half2*)&v[u]);
            int b = u & 3;
            ac[b][0] += pw[u] * f.x; ac[b][1] += pw[u] * f.y;
        }
    }
    if (k < deg) {
        size_t o0 = (size_t)sh_j[w][k] * 64 + co;
        uint32_t v[4] = {wh0[o0], wh1[o0], wh2[o0], wh3[o0]};
        float4 p0 = *(float4*)sh_e[w][k];
        float pw[4] = {p0.x * iv0, p0.y * iv1, p0.z * iv2, p0.w * iv3};
#pragma unroll
        for (int b = 0; b < 4; b++) {
            float2 f = __half22float2(*(__half2*)&v[b]);
            ac[b][0] += pw[b] * f.x; ac[b][1] += pw[b] * f.y;
        }
    }
#pragma unroll
    for (int b = 0; b < 4; b++)
        ((uint32_t*)&g_outh[((size_t)b * N_ + i) * DOUT_])[co] =
            pack_half(ac[b][0], ac[b][1]);
}

// ==== final: y = relu(adj @ out), warp per (row, half), 4 graphs fused =====
__global__ __launch_bounds__(256) void final_kernel(float* __restrict__ y) {
    int lane = threadIdx.x & 31;
    int w = threadIdx.x >> 5;
    int rl = w >> 1, half = w & 1;
    int i = blockIdx.x * 4 + rl;
    int deg = g_deg[i];
    int co = (half << 5) + lane;

    const uint32_t* ou0 = (const uint32_t*)g_outh;
    const uint32_t* ou1 = ou0 + (size_t)N_ * 64;
    const uint32_t* ou2 = ou1 + (size_t)N_ * 64;
    const uint32_t* ou3 = ou2 + (size_t)N_ * 64;
    float ac[4][2];
#pragma unroll
    for (int b = 0; b < 4; b++) { ac[b][0] = 0.f; ac[b][1] = 0.f; }

    int k = 0;
    for (; k + 2 <= deg; k += 2) {
        int j0 = g_cols[i * MAXDEG + k], j1 = g_cols[i * MAXDEG + k + 1];
        size_t o0 = (size_t)j0 * 64 + co, o1 = (size_t)j1 * 64 + co;
        uint32_t v[8];
        v[0] = ou0[o0]; v[1] = ou1[o0]; v[2] = ou2[o0]; v[3] = ou3[o0];
        v[4] = ou0[o1]; v[5] = ou1[o1]; v[6] = ou2[o1]; v[7] = ou3[o1];
#pragma unroll
        for (int u = 0; u < 8; u++) {
            float2 f = __half22float2(*(__half2*)&v[u]);
            int b = u & 3;
            ac[b][0] += f.x; ac[b][1] += f.y;
        }
    }
    if (k < deg) {
        size_t o0 = (size_t)g_cols[i * MAXDEG + k] * 64 + co;
        uint32_t v[4] = {ou0[o0], ou1[o0], ou2[o0], ou3[o0]};
#pragma unroll
        for (int b = 0; b < 4; b++) {
            float2 f = __half22float2(*(__half2*)&v[b]);
            ac[b][0] += f.x; ac[b][1] += f.y;
        }
    }
#pragma unroll
    for (int b = 0; b < 4; b++) {
        float2 r = make_float2(fmaxf(ac[b][0], 0.f), fmaxf(ac[b][1], 0.f));
        ((float2*)&y[((size_t)b * N_ + i) * DOUT_])[co] = r;
    }
}

// ---------------- launch ----------------
extern "C" void kernel_launch(void* const* d_in, const int* in_sizes, int n_in,
                              void* d_out, int out_size) {
    const float* x   = (const float*)d_in[0];  // (B, N, DIN)
    const float* adj = (const float*)d_in[1];  // (N, N)
    const float* wts = (const float*)d_in[2];  // (DIN, DOUT)
    const float* a   = (const float*)d_in[3];  // (2*DOUT, 1)
    float* y = (float*)d_out;

    static cudaStream_t s2;
    static cudaEvent_t evA, evC;
    static int inited = 0;
    if (!inited) {
        cudaFuncSetAttribute(gemm_hmma_kernel,
                             cudaFuncAttributeMaxDynamicSharedMemorySize, SMEM_TOTAL);
        cudaStreamCreateWithFlags(&s2, cudaStreamNonBlocking);
        cudaEventCreateWithFlags(&evA, cudaEventDisableTiming);
        cudaEventCreateWithFlags(&evC, cudaEventDisableTiming);
        inited = 1;
    }
    cudaStream_t s0 = 0;

    // fork: csr on s2 overlaps convW+GEMM on s0; join before attn
    cudaEventRecord(evA, s0);
    cudaStreamWaitEvent(s2, evA, 0);
    csr_build_kernel<<<N_ / 8, 256, 0, s2>>>(adj);
    cudaEventRecord(evC, s2);

    convw_kernel<<<DIN_ * DOUT_ / 1024, 256, 0, s0>>>(wts);
    gemm_hmma_kernel<<<(B_ * N_) / 128, 256, SMEM_TOTAL, s0>>>(x, a);
    cudaStreamWaitEvent(s0, evC, 0);

    attn_kernel<<<N_ / 4, 256, 0, s0>>>();
    final_kernel<<<N_ / 4, 256, 0, s0>>>(y);
}

// round 11
// speedup vs baseline: 1.4267x; 1.0968x over previous
#include <cuda_runtime.h>
#include <cuda_bf16.h>
#include <cuda_fp16.h>
#include <math.h>
#include <stdint.h>

#define B_    4
#define N_    4096
#define DIN_  512
#define DOUT_ 128
#define MAXDEG 128
#define NEG_BIG -1e30f

// ---------------- scratch (static device memory; no allocs) ----------------
__device__ __half g_whh[B_ * N_ * DOUT_];   // x @ W (fp16)   4 MB
__device__ __half g_outh[B_ * N_ * DOUT_];  // att @ wh       4 MB
__device__ float g_sT[N_ * 4];              // s transposed [i][b]
__device__ float g_dT[N_ * 4];              // d transposed [i][b]
__device__ float g_sumwh[B_ * DOUT_];       // per-graph colsum (deg==0 fallback)
__device__ int   g_cols[N_ * MAXDEG];
__device__ int   g_deg[N_];
__device__ uint32_t g_Wh[DIN_ * DOUT_ / 2]; // W as fp16x2 packed (128 KB)

// ============================ helpers =======================================
__device__ __forceinline__ uint32_t smem_u32(const void* p) {
    uint32_t a;
    asm("{ .reg .u64 t; cvta.to.shared.u64 t, %1; cvt.u32.u64 %0, t; }" : "=r"(a) : "l"(p));
    return a;
}
__device__ __forceinline__ void ldm_x4(uint32_t* f, uint32_t addr) {
    asm volatile("ldmatrix.sync.aligned.m8n8.x4.shared.b16 {%0,%1,%2,%3}, [%4];"
                 : "=r"(f[0]), "=r"(f[1]), "=r"(f[2]), "=r"(f[3]) : "r"(addr));
}
__device__ __forceinline__ void ldm_x4t(uint32_t* f, uint32_t addr) {
    asm volatile("ldmatrix.sync.aligned.m8n8.x4.trans.shared.b16 {%0,%1,%2,%3}, [%4];"
                 : "=r"(f[0]), "=r"(f[1]), "=r"(f[2]), "=r"(f[3]) : "r"(addr));
}
__device__ __forceinline__ void mma_f16(float* c, const uint32_t* a, const uint32_t* b) {
    asm volatile(
        "mma.sync.aligned.m16n8k16.row.col.f32.f16.f16.f32 "
        "{%0,%1,%2,%3}, {%4,%5,%6,%7}, {%8,%9}, {%0,%1,%2,%3};"
        : "+f"(c[0]), "+f"(c[1]), "+f"(c[2]), "+f"(c[3])
        : "r"(a[0]), "r"(a[1]), "r"(a[2]), "r"(a[3]), "r"(b[0]), "r"(b[1]));
}
__device__ __forceinline__ uint32_t pack_half(float x, float y) {
    __half2 h = __floats2half2_rn(x, y);
    return *(uint32_t*)&h;
}

// =============== W -> fp16 + zero g_sumwh ==================================
__global__ __launch_bounds__(256) void convw_kernel(const float* __restrict__ W) {
    if (blockIdx.x < 2) g_sumwh[blockIdx.x * 256 + threadIdx.x] = 0.0f;
    int i = blockIdx.x * 256 + threadIdx.x;     // 16384 float4s
    float4 v = ((const float4*)W)[i];
    g_Wh[i * 2]     = pack_half(v.x, v.y);
    g_Wh[i * 2 + 1] = pack_half(v.z, v.w);
}

// =============== CSR build: warp/row, 4 loads in flight ====================
__global__ void csr_build_kernel(const float* __restrict__ adj) {
    int warp = (blockIdx.x * blockDim.x + threadIdx.x) >> 5;
    int lane = threadIdx.x & 31;
    if (warp >= N_) return;
    const float4* row = (const float4*)(adj + (size_t)warp * N_);
    int cnt = 0;
    for (int base = 0; base < N_; base += 512) {
        float4 v0 = row[(base >> 2) + lane];
        float4 v1 = row[(base >> 2) + 32 + lane];
        float4 v2 = row[(base >> 2) + 64 + lane];
        float4 v3 = row[(base >> 2) + 96 + lane];
        float c16[16] = {v0.x, v0.y, v0.z, v0.w, v1.x, v1.y, v1.z, v1.w,
                         v2.x, v2.y, v2.z, v2.w, v3.x, v3.y, v3.z, v3.w};
#pragma unroll
        for (int h = 0; h < 4; h++) {
#pragma unroll
            for (int c = 0; c < 4; c++) {
                float f = c16[h * 4 + c];
                unsigned m = __ballot_sync(0xffffffffu, f > 0.0f);
                if (f > 0.0f) {
                    int pos = cnt + __popc(m & ((1u << lane) - 1u));
                    if (pos < MAXDEG)
                        g_cols[warp * MAXDEG + pos] = base + h * 128 + lane * 4 + c;
                }
                cnt += __popc(m);
            }
        }
    }
    if (lane == 0) g_deg[warp] = cnt < MAXDEG ? cnt : MAXDEG;
}

// ===== HMMA GEMM (pure fp16): wh = x @ W ===================================
#define KC 32
#define NCH (DIN_ / KC)
#define A_STG 16384              // 128 rows * 128B (hi only; layout keeps swizzle)
#define B_STG 8192               // 32 k * 128 n * 2B
#define SM_A 0
#define SM_B (2 * A_STG)
#define SM_SD (SM_B + 2 * B_STG)
#define SM_AV (SM_SD + 1024)
#define SM_CS (SM_AV + 1024)
#define SMEM_TOTAL (SM_CS + 512)

__device__ __forceinline__ uint32_t a_off(int r, int gran) {
    return (uint32_t)(r * 128 + ((gran ^ (r & 7)) << 4));
}
__device__ __forceinline__ uint32_t b_off2(int k, int gran) {
    return (uint32_t)(k * 256 + ((gran ^ (k & 7)) << 4));
}

__global__ __launch_bounds__(256, 1) void gemm_hmma_kernel(
    const float* __restrict__ x, const float* __restrict__ a) {
    extern __shared__ char smem[];
    const uint32_t sb = smem_u32(smem);
    const int tid = threadIdx.x;
    const int wid = tid >> 5, lane = tid & 31;
    const int wm = wid >> 1, wn = wid & 1;
    const int tig = lane & 3, grp = lane >> 2;

    float* s_sm = (float*)(smem + SM_SD);
    float* d_sm = (float*)(smem + SM_SD + 512);
    float* a_s  = (float*)(smem + SM_AV);
    float* a_d  = (float*)(smem + SM_AV + 512);
    float* cs   = (float*)(smem + SM_CS);
    if (tid < 128) {
        s_sm[tid] = 0.0f; d_sm[tid] = 0.0f; cs[tid] = 0.0f;
        a_s[tid] = a[tid]; a_d[tid] = a[DOUT_ + tid];
    }

    const int R0 = blockIdx.x * 128;
    const int arow = tid >> 1, akoff = (tid & 1) * 16;
    const float* pA = x + (size_t)(R0 + arow) * DIN_ + akoff;
    const int bk = tid >> 3, bgr = (tid & 7) * 2;
    const uint4* Wh4 = (const uint4*)g_Wh;

    float acc[2][8][4];
#pragma unroll
    for (int i = 0; i < 2; i++)
#pragma unroll
        for (int j = 0; j < 8; j++)
#pragma unroll
            for (int q = 0; q < 4; q++) acc[i][j][q] = 0.0f;

    float4 ra[4];
    uint4 rbh[2];
#pragma unroll
    for (int i = 0; i < 4; i++) ra[i] = *(const float4*)(pA + i * 4);
    {
        int gi = bk * 16 + bgr;
        rbh[0] = Wh4[gi];  rbh[1] = Wh4[gi + 1];
    }

    for (int c = 0; c < NCH; c++) {
        const int buf = c & 1;
        char* Abuf = smem + SM_A + buf * A_STG;
        char* Bbuf = smem + SM_B + buf * B_STG;

        {
            const float* fa = (const float*)ra;
#pragma unroll
            for (int p = 0; p < 8; p++) {
                float f0 = fa[2 * p], f1 = fa[2 * p + 1];
                uint32_t hv = pack_half(f0, f1);
                int kl = akoff + 2 * p;
                int gr = kl >> 3, wi = (kl & 7) * 2;
                *(uint32_t*)(Abuf + a_off(arow, gr) + wi) = hv;
            }
            *(uint4*)(Bbuf + b_off2(bk, bgr))     = rbh[0];
            *(uint4*)(Bbuf + b_off2(bk, bgr + 1)) = rbh[1];
        }
        __syncthreads();

        if (c + 1 < NCH) {
            const float* qA = pA + (c + 1) * KC;
#pragma unroll
            for (int i = 0; i < 4; i++) ra[i] = *(const float4*)(qA + i * 4);
            int gi = (c + 1) * 512 + bk * 16 + bgr;
            rbh[0] = Wh4[gi];  rbh[1] = Wh4[gi + 1];
        }

        const uint32_t Abase = sb + SM_A + buf * A_STG;
        const uint32_t Bbase = sb + SM_B + buf * B_STG;
#pragma unroll
        for (int ks = 0; ks < 2; ks++) {
            uint32_t ahi[2][4];
#pragma unroll
            for (int mt = 0; mt < 2; mt++) {
                int R = wm * 32 + mt * 16 + (lane & 15);
                int gh = 2 * ks + (lane >> 4);
                ldm_x4(ahi[mt], Abase + a_off(R, gh));
            }
            int kk = 16 * ks + (lane & 15);
#pragma unroll
            for (int ntp = 0; ntp < 4; ntp++) {
                int gn = wn * 8 + ntp * 2 + (lane >> 4);
                uint32_t bb[4];
                ldm_x4t(bb, Bbase + b_off2(kk, gn));
#pragma unroll
                for (int mt = 0; mt < 2; mt++) {
                    mma_f16(acc[mt][ntp * 2],     ahi[mt], bb);
                    mma_f16(acc[mt][ntp * 2 + 1], ahi[mt], bb + 2);
                }
            }
        }
        __syncthreads();
    }

    // ---- epilogue: store wh (fp16), fused s/d dots + column sums ----
    float sacc[2][2] = {{0, 0}, {0, 0}}, dacc[2][2] = {{0, 0}, {0, 0}};
#pragma unroll
    for (int mt = 0; mt < 2; mt++) {
        int rbase = R0 + wm * 32 + mt * 16 + grp;
#pragma unroll
        for (int nt = 0; nt < 8; nt++) {
            int col = wn * 64 + nt * 8 + tig * 2;
            float* cf = acc[mt][nt];
            sacc[mt][0] += cf[0] * a_s[col] + cf[1] * a_s[col + 1];
            sacc[mt][1] += cf[2] * a_s[col] + cf[3] * a_s[col + 1];
            dacc[mt][0] += cf[0] * a_d[col] + cf[1] * a_d[col + 1];
            dacc[mt][1] += cf[2] * a_d[col] + cf[3] * a_d[col + 1];
            *(__half2*)&g_whh[(size_t)rbase * DOUT_ + col] =
                __float22half2_rn(make_float2(cf[0], cf[1]));
            *(__half2*)&g_whh[(size_t)(rbase + 8) * DOUT_ + col] =
                __float22half2_rn(make_float2(cf[2], cf[3]));

            float v0 = cf[0] + cf[2];
            float v1 = cf[1] + cf[3];
#pragma unroll
            for (int off = 16; off >= 4; off >>= 1) {
                v0 += __shfl_down_sync(0xffffffffu, v0, off);
                v1 += __shfl_down_sync(0xffffffffu, v1, off);
            }
            if (lane < 4) {
                atomicAdd(&cs[col], v0);
                atomicAdd(&cs[col + 1], v1);
            }
        }
    }
#pragma unroll
    for (int mt = 0; mt < 2; mt++)
#pragma unroll
        for (int h = 0; h < 2; h++) {
            sacc[mt][h] += __shfl_xor_sync(0xffffffffu, sacc[mt][h], 1);
            sacc[mt][h] += __shfl_xor_sync(0xffffffffu, sacc[mt][h], 2);
            dacc[mt][h] += __shfl_xor_sync(0xffffffffu, dacc[mt][h], 1);
            dacc[mt][h] += __shfl_xor_sync(0xffffffffu, dacc[mt][h], 2);
        }
    if (tig == 0) {
#pragma unroll
        for (int mt = 0; mt < 2; mt++) {
            int r = wm * 32 + mt * 16 + grp;
            atomicAdd(&s_sm[r], sacc[mt][0]);
            atomicAdd(&s_sm[r + 8], sacc[mt][1]);
            atomicAdd(&d_sm[r], dacc[mt][0]);
            atomicAdd(&d_sm[r + 8], dacc[mt][1]);
        }
    }
    __syncthreads();
    if (tid < 128) {
        int b = R0 / N_;
        int il = (R0 % N_) + tid;
        g_sT[il * 4 + b] = s_sm[tid];
        g_dT[il * 4 + b] = d_sm[tid];
        atomicAdd(&g_sumwh[b * DOUT_ + tid], cs[tid]);
    }
}

// ==== attention SpMM: warp per (row, graph-pair) — no duplicated softmax ===
__global__ __launch_bounds__(256) void attn_kernel() {
    __shared__ float sh_e[8][MAXDEG][2];   // 8 KB (per-warp private)
    __shared__ int   sh_j[8][MAXDEG];      // 4 KB (per-warp private)
    int lane = threadIdx.x & 31;
    int w = threadIdx.x >> 5;
    int rl = w >> 1, pr = w & 1;           // pr: graph pair {0,1} -> graphs 2pr, 2pr+1
    int i = blockIdx.x * 4 + rl;
    int deg = g_deg[i];
    int b0 = 2 * pr;

    if (deg == 0) {
        float inv = 1.0f / (float)N_;
#pragma unroll
        for (int q = 0; q < 2; q++) {
            int b = b0 + q;
            float4 m = ((const float4*)&g_sumwh[b * DOUT_])[lane];
            uint2 o;
            o.x = pack_half(m.x * inv, m.y * inv);
            o.y = pack_half(m.z * inv, m.w * inv);
            ((uint2*)&g_outh[((size_t)b * N_ + i) * DOUT_])[lane] = o;
        }
        return;
    }

    float2 s2 = *(const float2*)&g_sT[i * 4 + b0];
    float mx0 = NEG_BIG, mx1 = NEG_BIG;
    for (int t = lane; t < deg; t += 32) {
        int j = g_cols[i * MAXDEG + t];
        sh_j[w][t] = j;
        float2 d2 = *(const float2*)&g_dT[j * 4 + b0];
        float e0 = s2.x + d2.x; e0 = e0 > 0.f ? e0 : 0.01f * e0;
        float e1 = s2.y + d2.y; e1 = e1 > 0.f ? e1 : 0.01f * e1;
        *(float2*)sh_e[w][t] = make_float2(e0, e1);
        mx0 = fmaxf(mx0, e0); mx1 = fmaxf(mx1, e1);
    }
#pragma unroll
    for (int off = 16; off > 0; off >>= 1) {
        mx0 = fmaxf(mx0, __shfl_xor_sync(0xffffffffu, mx0, off));
        mx1 = fmaxf(mx1, __shfl_xor_sync(0xffffffffu, mx1, off));
    }
    __syncwarp();

    float se0 = 0.f, se1 = 0.f;
    for (int t = lane; t < deg; t += 32) {
        float2 e = *(float2*)sh_e[w][t];
        float p0 = __expf(e.x - mx0), p1 = __expf(e.y - mx1);
        *(float2*)sh_e[w][t] = make_float2(p0, p1);
        se0 += p0; se1 += p1;
    }
#pragma unroll
    for (int off = 16; off > 0; off >>= 1) {
        se0 += __shfl_xor_sync(0xffffffffu, se0, off);
        se1 += __shfl_xor_sync(0xffffffffu, se1, off);
    }
    float iv0 = 1.f / se0, iv1 = 1.f / se1;
    __syncwarp();

    const uint2* whA = (const uint2*)g_whh + (size_t)b0 * N_ * 32;
    const uint2* whB = whA + (size_t)N_ * 32;
    float aA0 = 0.f, aA1 = 0.f, aA2 = 0.f, aA3 = 0.f;
    float aB0 = 0.f, aB1 = 0.f, aB2 = 0.f, aB3 = 0.f;

    int k = 0;
    for (; k + 2 <= deg; k += 2) {
        int j0 = sh_j[w][k], j1 = sh_j[w][k + 1];
        size_t o0 = (size_t)j0 * 32 + lane, o1 = (size_t)j1 * 32 + lane;
        uint2 vA0 = whA[o0], vB0 = whB[o0];
        uint2 vA1 = whA[o1], vB1 = whB[o1];
        float2 p0 = *(float2*)sh_e[w][k];
        float2 p1 = *(float2*)sh_e[w][k + 1];
        float pA0 = p0.x * iv0, pB0 = p0.y * iv1;
        float pA1 = p1.x * iv0, pB1 = p1.y * iv1;
        float2 f;
        f = __half22float2(*(__half2*)&vA0.x); aA0 += pA0 * f.x; aA1 += pA0 * f.y;
        f = __half22float2(*(__half2*)&vA0.y); aA2 += pA0 * f.x; aA3 += pA0 * f.y;
        f = __half22float2(*(__half2*)&vB0.x); aB0 += pB0 * f.x; aB1 += pB0 * f.y;
        f = __half22float2(*(__half2*)&vB0.y); aB2 += pB0 * f.x; aB3 += pB0 * f.y;
        f = __half22float2(*(__half2*)&vA1.x); aA0 += pA1 * f.x; aA1 += pA1 * f.y;
        f = __half22float2(*(__half2*)&vA1.y); aA2 += pA1 * f.x; aA3 += pA1 * f.y;
        f = __half22float2(*(__half2*)&vB1.x); aB0 += pB1 * f.x; aB1 += pB1 * f.y;
        f = __half22float2(*(__half2*)&vB1.y); aB2 += pB1 * f.x; aB3 += pB1 * f.y;
    }
    if (k < deg) {
        size_t o0 = (size_t)sh_j[w][k] * 32 + lane;
        uint2 vA0 = whA[o0], vB0 = whB[o0];
        float2 p0 = *(float2*)sh_e[w][k];
        float pA0 = p0.x * iv0, pB0 = p0.y * iv1;
        float2 f;
        f = __half22float2(*(__half2*)&vA0.x); aA0 += pA0 * f.x; aA1 += pA0 * f.y;
        f = __half22float2(*(__half2*)&vA0.y); aA2 += pA0 * f.x; aA3 += pA0 * f.y;
        f = __half22float2(*(__half2*)&vB0.x); aB0 += pB0 * f.x; aB1 += pB0 * f.y;
        f = __half22float2(*(__half2*)&vB0.y); aB2 += pB0 * f.x; aB3 += pB0 * f.y;
    }
    uint2 oA, oB;
    oA.x = pack_half(aA0, aA1); oA.y = pack_half(aA2, aA3);
    oB.x = pack_half(aB0, aB1); oB.y = pack_half(aB2, aB3);
    ((uint2*)&g_outh[((size_t)b0 * N_ + i) * DOUT_])[lane] = oA;
    ((uint2*)&g_outh[((size_t)(b0 + 1) * N_ + i) * DOUT_])[lane] = oB;
}

// ==== final: y = relu(adj @ out), warp per (row, graph-pair) ================
__global__ __launch_bounds__(256) void final_kernel(float* __restrict__ y) {
    int lane = threadIdx.x & 31;
    int w = threadIdx.x >> 5;
    int rl = w >> 1, pr = w & 1;
    int i = blockIdx.x * 4 + rl;
    int deg = g_deg[i];
    int b0 = 2 * pr;

    const uint2* ouA = (const uint2*)g_outh + (size_t)b0 * N_ * 32;
    const uint2* ouB = ouA + (size_t)N_ * 32;
    float aA0 = 0.f, aA1 = 0.f, aA2 = 0.f, aA3 = 0.f;
    float aB0 = 0.f, aB1 = 0.f, aB2 = 0.f, aB3 = 0.f;

    int k = 0;
    for (; k + 2 <= deg; k += 2) {
        int j0 = g_cols[i * MAXDEG + k], j1 = g_cols[i * MAXDEG + k + 1];
        size_t o0 = (size_t)j0 * 32 + lane, o1 = (size_t)j1 * 32 + lane;
        uint2 vA0 = ouA[o0], vB0 = ouB[o0];
        uint2 vA1 = ouA[o1], vB1 = ouB[o1];
        float2 f;
        f = __half22float2(*(__half2*)&vA0.x); aA0 += f.x; aA1 += f.y;
        f = __half22float2(*(__half2*)&vA0.y); aA2 += f.x; aA3 += f.y;
        f = __half22float2(*(__half2*)&vB0.x); aB0 += f.x; aB1 += f.y;
        f = __half22float2(*(__half2*)&vB0.y); aB2 += f.x; aB3 += f.y;
        f = __half22float2(*(__half2*)&vA1.x); aA0 += f.x; aA1 += f.y;
        f = __half22float2(*(__half2*)&vA1.y); aA2 += f.x; aA3 += f.y;
        f = __half22float2(*(__half2*)&vB1.x); aB0 += f.x; aB1 += f.y;
        f = __half22float2(*(__half2*)&vB1.y); aB2 += f.x; aB3 += f.y;
    }
    if (k < deg) {
        size_t o0 = (size_t)g_cols[i * MAXDEG + k] * 32 + lane;
        uint2 vA0 = ouA[o0], vB0 = ouB[o0];
        float2 f;
        f = __half22float2(*(__half2*)&vA0.x); aA0 += f.x; aA1 += f.y;
        f = __half22float2(*(__half2*)&vA0.y); aA2 += f.x; aA3 += f.y;
        f = __half22float2(*(__half2*)&vB0.x); aB0 += f.x; aB1 += f.y;
        f = __half22float2(*(__half2*)&vB0.y); aB2 += f.x; aB3 += f.y;
    }
    float4 rA = make_float4(fmaxf(aA0, 0.f), fmaxf(aA1, 0.f),
                            fmaxf(aA2, 0.f), fmaxf(aA3, 0.f));
    float4 rB = make_float4(fmaxf(aB0, 0.f), fmaxf(aB1, 0.f),
                            fmaxf(aB2, 0.f), fmaxf(aB3, 0.f));
    ((float4*)&y[((size_t)b0 * N_ + i) * DOUT_])[lane] = rA;
    ((float4*)&y[((size_t)(b0 + 1) * N_ + i) * DOUT_])[lane] = rB;
}

// ---------------- launch ----------------
extern "C" void kernel_launch(void* const* d_in, const int* in_sizes, int n_in,
                              void* d_out, int out_size) {
    const float* x   = (const float*)d_in[0];  // (B, N, DIN)
    const float* adj = (const float*)d_in[1];  // (N, N)
    const float* wts = (const float*)d_in[2];  // (DIN, DOUT)
    const float* a   = (const float*)d_in[3];  // (2*DOUT, 1)
    float* y = (float*)d_out;

    static cudaStream_t s2;
    static cudaEvent_t evA, evC;
    static int inited = 0;
    if (!inited) {
        cudaFuncSetAttribute(gemm_hmma_kernel,
                             cudaFuncAttributeMaxDynamicSharedMemorySize, SMEM_TOTAL);
        cudaStreamCreateWithFlags(&s2, cudaStreamNonBlocking);
        cudaEventCreateWithFlags(&evA, cudaEventDisableTiming);
        cudaEventCreateWithFlags(&evC, cudaEventDisableTiming);
        inited = 1;
    }
    cudaStream_t s0 = 0;

    // fork: csr on s2 overlaps convW+GEMM on s0; join before attn
    cudaEventRecord(evA, s0);
    cudaStreamWaitEvent(s2, evA, 0);
    csr_build_kernel<<<N_ / 8, 256, 0, s2>>>(adj);
    cudaEventRecord(evC, s2);

    convw_kernel<<<DIN_ * DOUT_ / 1024, 256, 0, s0>>>(wts);
    gemm_hmma_kernel<<<(B_ * N_) / 128, 256, SMEM_TOTAL, s0>>>(x, a);
    cudaStreamWaitEvent(s0, evC, 0);

    attn_kernel<<<N_ / 4, 256, 0, s0>>>();
    final_kernel<<<N_ / 4, 256, 0, s0>>>(y);
}

// round 12
// speedup vs baseline: 1.5161x; 1.0626x over previous
#include <cuda_runtime.h>
#include <cuda_bf16.h>
#include <cuda_fp16.h>
#include <math.h>
#include <stdint.h>

#define B_    4
#define N_    4096
#define DIN_  512
#define DOUT_ 128
#define MAXDEG 128
#define NEG_BIG -1e30f

// ---------------- scratch (static device memory; no allocs) ----------------
__device__ __half g_whh[B_ * N_ * DOUT_];   // x @ W (fp16)   4 MB
__device__ __half g_outh[B_ * N_ * DOUT_];  // att @ wh       4 MB
__device__ float g_sT[N_ * 4];              // s transposed [i][b]
__device__ float g_dT[N_ * 4];              // d transposed [i][b]
__device__ float g_sumwh[B_ * DOUT_];       // per-graph colsum (deg==0 fallback)
__device__ int   g_cols[N_ * MAXDEG];
__device__ int   g_deg[N_];
__device__ uint32_t g_Wh[DIN_ * DOUT_ / 2]; // W as fp16x2 packed (128 KB)

// ============================ helpers =======================================
__device__ __forceinline__ uint32_t smem_u32(const void* p) {
    uint32_t a;
    asm("{ .reg .u64 t; cvta.to.shared.u64 t, %1; cvt.u32.u64 %0, t; }" : "=r"(a) : "l"(p));
    return a;
}
__device__ __forceinline__ void ldm_x4(uint32_t* f, uint32_t addr) {
    asm volatile("ldmatrix.sync.aligned.m8n8.x4.shared.b16 {%0,%1,%2,%3}, [%4];"
                 : "=r"(f[0]), "=r"(f[1]), "=r"(f[2]), "=r"(f[3]) : "r"(addr));
}
__device__ __forceinline__ void ldm_x4t(uint32_t* f, uint32_t addr) {
    asm volatile("ldmatrix.sync.aligned.m8n8.x4.trans.shared.b16 {%0,%1,%2,%3}, [%4];"
                 : "=r"(f[0]), "=r"(f[1]), "=r"(f[2]), "=r"(f[3]) : "r"(addr));
}
__device__ __forceinline__ void mma_f16(float* c, const uint32_t* a, const uint32_t* b) {
    asm volatile(
        "mma.sync.aligned.m16n8k16.row.col.f32.f16.f16.f32 "
        "{%0,%1,%2,%3}, {%4,%5,%6,%7}, {%8,%9}, {%0,%1,%2,%3};"
        : "+f"(c[0]), "+f"(c[1]), "+f"(c[2]), "+f"(c[3])
        : "r"(a[0]), "r"(a[1]), "r"(a[2]), "r"(a[3]), "r"(b[0]), "r"(b[1]));
}
__device__ __forceinline__ uint32_t pack_half(float x, float y) {
    __half2 h = __floats2half2_rn(x, y);
    return *(uint32_t*)&h;
}

// =============== W -> fp16 + zero g_sumwh ==================================
__global__ __launch_bounds__(256) void convw_kernel(const float* __restrict__ W) {
    if (blockIdx.x < 2) g_sumwh[blockIdx.x * 256 + threadIdx.x] = 0.0f;
    int i = blockIdx.x * 256 + threadIdx.x;     // 16384 float4s
    float4 v = ((const float4*)W)[i];
    g_Wh[i * 2]     = pack_half(v.x, v.y);
    g_Wh[i * 2 + 1] = pack_half(v.z, v.w);
}

// =============== CSR build: warp/row, 4 loads in flight ====================
__global__ void csr_build_kernel(const float* __restrict__ adj) {
    int warp = (blockIdx.x * blockDim.x + threadIdx.x) >> 5;
    int lane = threadIdx.x & 31;
    if (warp >= N_) return;
    const float4* row = (const float4*)(adj + (size_t)warp * N_);
    int cnt = 0;
    for (int base = 0; base < N_; base += 512) {
        float4 v0 = row[(base >> 2) + lane];
        float4 v1 = row[(base >> 2) + 32 + lane];
        float4 v2 = row[(base >> 2) + 64 + lane];
        float4 v3 = row[(base >> 2) + 96 + lane];
        float c16[16] = {v0.x, v0.y, v0.z, v0.w, v1.x, v1.y, v1.z, v1.w,
                         v2.x, v2.y, v2.z, v2.w, v3.x, v3.y, v3.z, v3.w};
#pragma unroll
        for (int h = 0; h < 4; h++) {
#pragma unroll
            for (int c = 0; c < 4; c++) {
                float f = c16[h * 4 + c];
                unsigned m = __ballot_sync(0xffffffffu, f > 0.0f);
                if (f > 0.0f) {
                    int pos = cnt + __popc(m & ((1u << lane) - 1u));
                    if (pos < MAXDEG)
                        g_cols[warp * MAXDEG + pos] = base + h * 128 + lane * 4 + c;
                }
                cnt += __popc(m);
            }
        }
    }
    if (lane == 0) g_deg[warp] = cnt < MAXDEG ? cnt : MAXDEG;
}

// ===== HMMA GEMM (fp16): wh = x @ W.  M-tile 64 -> 256 CTAs, 2/SM ==========
#define KC 32
#define NCH (DIN_ / KC)          // 16
#define A_STG 8192               // 64 rows * 128B
#define B_STG 8192               // 32 k * 128 n * 2B
#define SM_A 0
#define SM_B (2 * A_STG)
#define SM_SD (SM_B + 2 * B_STG)          // s_sm[64], d_sm[64]
#define SM_AV (SM_SD + 512)               // a_s[128], a_d[128]
#define SM_CS (SM_AV + 1024)              // cs[128]
#define SMEM_TOTAL (SM_CS + 512)

__device__ __forceinline__ uint32_t a_off(int r, int gran) {
    return (uint32_t)(r * 128 + ((gran ^ (r & 7)) << 4));
}
__device__ __forceinline__ uint32_t b_off2(int k, int gran) {
    return (uint32_t)(k * 256 + ((gran ^ (k & 7)) << 4));
}

__global__ __launch_bounds__(256, 2) void gemm_hmma_kernel(
    const float* __restrict__ x, const float* __restrict__ a) {
    extern __shared__ char smem[];
    const uint32_t sb = smem_u32(smem);
    const int tid = threadIdx.x;
    const int wid = tid >> 5, lane = tid & 31;
    const int wm = wid >> 1, wn = wid & 1;     // warp tile: 16 rows x 64 cols
    const int tig = lane & 3, grp = lane >> 2;

    float* s_sm = (float*)(smem + SM_SD);
    float* d_sm = (float*)(smem + SM_SD + 256);
    float* a_s  = (float*)(smem + SM_AV);
    float* a_d  = (float*)(smem + SM_AV + 512);
    float* cs   = (float*)(smem + SM_CS);
    if (tid < 128) {
        cs[tid] = 0.0f;
        a_s[tid] = a[tid]; a_d[tid] = a[DOUT_ + tid];
    }
    if (tid < 64) { s_sm[tid] = 0.0f; d_sm[tid] = 0.0f; }

    const int R0 = blockIdx.x * 64;
    const int arow = tid >> 2, akoff = (tid & 3) * 8;   // 4 threads/row, 8 floats each
    const float* pA = x + (size_t)(R0 + arow) * DIN_ + akoff;
    const int bk = tid >> 3, bgr = (tid & 7) * 2;
    const uint4* Wh4 = (const uint4*)g_Wh;

    float acc[8][4];
#pragma unroll
    for (int j = 0; j < 8; j++)
#pragma unroll
        for (int q = 0; q < 4; q++) acc[j][q] = 0.0f;

    float4 ra[2];
    uint4 rbh[2];
    ra[0] = *(const float4*)(pA);
    ra[1] = *(const float4*)(pA + 4);
    {
        int gi = bk * 16 + bgr;
        rbh[0] = Wh4[gi];  rbh[1] = Wh4[gi + 1];
    }

    for (int c = 0; c < NCH; c++) {
        const int buf = c & 1;
        char* Abuf = smem + SM_A + buf * A_STG;
        char* Bbuf = smem + SM_B + buf * B_STG;

        {
            const float* fa = (const float*)ra;
#pragma unroll
            for (int p = 0; p < 4; p++) {
                uint32_t hv = pack_half(fa[2 * p], fa[2 * p + 1]);
                int kl = akoff + 2 * p;
                int gr = kl >> 3, wi = (kl & 7) * 2;
                *(uint32_t*)(Abuf + a_off(arow, gr) + wi) = hv;
            }
            *(uint4*)(Bbuf + b_off2(bk, bgr))     = rbh[0];
            *(uint4*)(Bbuf + b_off2(bk, bgr + 1)) = rbh[1];
        }
        __syncthreads();

        if (c + 1 < NCH) {
            const float* qA = pA + (c + 1) * KC;
            ra[0] = *(const float4*)(qA);
            ra[1] = *(const float4*)(qA + 4);
            int gi = (c + 1) * 512 + bk * 16 + bgr;
            rbh[0] = Wh4[gi];  rbh[1] = Wh4[gi + 1];
        }

        const uint32_t Abase = sb + SM_A + buf * A_STG;
        const uint32_t Bbase = sb + SM_B + buf * B_STG;
#pragma unroll
        for (int ks = 0; ks < 2; ks++) {
            uint32_t ahi[4];
            {
                int R = wm * 16 + (lane & 15);
                int gh = 2 * ks + (lane >> 4);
                ldm_x4(ahi, Abase + a_off(R, gh));
            }
            int kk = 16 * ks + (lane & 15);
#pragma unroll
            for (int ntp = 0; ntp < 4; ntp++) {
                int gn = wn * 8 + ntp * 2 + (lane >> 4);
                uint32_t bb[4];
                ldm_x4t(bb, Bbase + b_off2(kk, gn));
                mma_f16(acc[ntp * 2],     ahi, bb);
                mma_f16(acc[ntp * 2 + 1], ahi, bb + 2);
            }
        }
        __syncthreads();
    }

    // ---- epilogue: store wh (fp16), fused s/d dots + column sums ----
    float sacc[2] = {0, 0}, dacc[2] = {0, 0};
    int rbase = R0 + wm * 16 + grp;
#pragma unroll
    for (int nt = 0; nt < 8; nt++) {
        int col = wn * 64 + nt * 8 + tig * 2;
        float* cf = acc[nt];
        sacc[0] += cf[0] * a_s[col] + cf[1] * a_s[col + 1];
        sacc[1] += cf[2] * a_s[col] + cf[3] * a_s[col + 1];
        dacc[0] += cf[0] * a_d[col] + cf[1] * a_d[col + 1];
        dacc[1] += cf[2] * a_d[col] + cf[3] * a_d[col + 1];
        *(__half2*)&g_whh[(size_t)rbase * DOUT_ + col] =
            __float22half2_rn(make_float2(cf[0], cf[1]));
        *(__half2*)&g_whh[(size_t)(rbase + 8) * DOUT_ + col] =
            __float22half2_rn(make_float2(cf[2], cf[3]));

        float v0 = cf[0] + cf[2];
        float v1 = cf[1] + cf[3];
#pragma unroll
        for (int off = 16; off >= 4; off >>= 1) {
            v0 += __shfl_down_sync(0xffffffffu, v0, off);
            v1 += __shfl_down_sync(0xffffffffu, v1, off);
        }
        if (lane < 4) {
            atomicAdd(&cs[col], v0);
            atomicAdd(&cs[col + 1], v1);
        }
    }
#pragma unroll
    for (int h = 0; h < 2; h++) {
        sacc[h] += __shfl_xor_sync(0xffffffffu, sacc[h], 1);
        sacc[h] += __shfl_xor_sync(0xffffffffu, sacc[h], 2);
        dacc[h] += __shfl_xor_sync(0xffffffffu, dacc[h], 1);
        dacc[h] += __shfl_xor_sync(0xffffffffu, dacc[h], 2);
    }
    if (tig == 0) {
        int r = wm * 16 + grp;
        atomicAdd(&s_sm[r], sacc[0]);
        atomicAdd(&s_sm[r + 8], sacc[1]);
        atomicAdd(&d_sm[r], dacc[0]);
        atomicAdd(&d_sm[r + 8], dacc[1]);
    }
    __syncthreads();
    if (tid < 64) {
        int b = R0 / N_;
        int il = (R0 % N_) + tid;
        g_sT[il * 4 + b] = s_sm[tid];
        g_dT[il * 4 + b] = d_sm[tid];
    }
    if (tid < 128) {
        int b = R0 / N_;
        atomicAdd(&g_sumwh[b * DOUT_ + tid], cs[tid]);
    }
}

// ==== attention SpMM: warp per (row, graph-pair), 4-edge unrolled ==========
__global__ __launch_bounds__(256) void attn_kernel() {
    __shared__ float sh_e[8][MAXDEG][2];
    __shared__ int   sh_j[8][MAXDEG];
    int lane = threadIdx.x & 31;
    int w = threadIdx.x >> 5;
    int rl = w >> 1, pr = w & 1;
    int i = blockIdx.x * 4 + rl;
    int deg = g_deg[i];
    int b0 = 2 * pr;

    if (deg == 0) {
        float inv = 1.0f / (float)N_;
#pragma unroll
        for (int q = 0; q < 2; q++) {
            int b = b0 + q;
            float4 m = ((const float4*)&g_sumwh[b * DOUT_])[lane];
            uint2 o;
            o.x = pack_half(m.x * inv, m.y * inv);
            o.y = pack_half(m.z * inv, m.w * inv);
            ((uint2*)&g_outh[((size_t)b * N_ + i) * DOUT_])[lane] = o;
        }
        return;
    }

    float2 s2 = *(const float2*)&g_sT[i * 4 + b0];
    float mx0 = NEG_BIG, mx1 = NEG_BIG;
    for (int t = lane; t < deg; t += 32) {
        int j = g_cols[i * MAXDEG + t];
        sh_j[w][t] = j;
        float2 d2 = *(const float2*)&g_dT[j * 4 + b0];
        float e0 = s2.x + d2.x; e0 = e0 > 0.f ? e0 : 0.01f * e0;
        float e1 = s2.y + d2.y; e1 = e1 > 0.f ? e1 : 0.01f * e1;
        *(float2*)sh_e[w][t] = make_float2(e0, e1);
        mx0 = fmaxf(mx0, e0); mx1 = fmaxf(mx1, e1);
    }
#pragma unroll
    for (int off = 16; off > 0; off >>= 1) {
        mx0 = fmaxf(mx0, __shfl_xor_sync(0xffffffffu, mx0, off));
        mx1 = fmaxf(mx1, __shfl_xor_sync(0xffffffffu, mx1, off));
    }
    __syncwarp();

    float se0 = 0.f, se1 = 0.f;
    for (int t = lane; t < deg; t += 32) {
        float2 e = *(float2*)sh_e[w][t];
        float p0 = __expf(e.x - mx0), p1 = __expf(e.y - mx1);
        *(float2*)sh_e[w][t] = make_float2(p0, p1);
        se0 += p0; se1 += p1;
    }
#pragma unroll
    for (int off = 16; off > 0; off >>= 1) {
        se0 += __shfl_xor_sync(0xffffffffu, se0, off);
        se1 += __shfl_xor_sync(0xffffffffu, se1, off);
    }
    float iv0 = 1.f / se0, iv1 = 1.f / se1;
    __syncwarp();

    const uint2* whA = (const uint2*)g_whh + (size_t)b0 * N_ * 32;
    const uint2* whB = whA + (size_t)N_ * 32;
    float aA0 = 0.f, aA1 = 0.f, aA2 = 0.f, aA3 = 0.f;
    float aB0 = 0.f, aB1 = 0.f, aB2 = 0.f, aB3 = 0.f;

    int k = 0;
    for (; k + 4 <= deg; k += 4) {
        uint2 vA[4], vB[4];
        float pA[4], pB[4];
#pragma unroll
        for (int u = 0; u < 4; u++) {
            size_t o = (size_t)sh_j[w][k + u] * 32 + lane;
            vA[u] = whA[o]; vB[u] = whB[o];
            float2 p = *(float2*)sh_e[w][k + u];
            pA[u] = p.x * iv0; pB[u] = p.y * iv1;
        }
#pragma unroll
        for (int u = 0; u < 4; u++) {
            float2 f;
            f = __half22float2(*(__half2*)&vA[u].x); aA0 += pA[u] * f.x; aA1 += pA[u] * f.y;
            f = __half22float2(*(__half2*)&vA[u].y); aA2 += pA[u] * f.x; aA3 += pA[u] * f.y;
            f = __half22float2(*(__half2*)&vB[u].x); aB0 += pB[u] * f.x; aB1 += pB[u] * f.y;
            f = __half22float2(*(__half2*)&vB[u].y); aB2 += pB[u] * f.x; aB3 += pB[u] * f.y;
        }
    }
    for (; k < deg; k++) {
        size_t o0 = (size_t)sh_j[w][k] * 32 + lane;
        uint2 vA0 = whA[o0], vB0 = whB[o0];
        float2 p0 = *(float2*)sh_e[w][k];
        float pA0 = p0.x * iv0, pB0 = p0.y * iv1;
        float2 f;
        f = __half22float2(*(__half2*)&vA0.x); aA0 += pA0 * f.x; aA1 += pA0 * f.y;
        f = __half22float2(*(__half2*)&vA0.y); aA2 += pA0 * f.x; aA3 += pA0 * f.y;
        f = __half22float2(*(__half2*)&vB0.x); aB0 += pB0 * f.x; aB1 += pB0 * f.y;
        f = __half22float2(*(__half2*)&vB0.y); aB2 += pB0 * f.x; aB3 += pB0 * f.y;
    }
    uint2 oA, oB;
    oA.x = pack_half(aA0, aA1); oA.y = pack_half(aA2, aA3);
    oB.x = pack_half(aB0, aB1); oB.y = pack_half(aB2, aB3);
    ((uint2*)&g_outh[((size_t)b0 * N_ + i) * DOUT_])[lane] = oA;
    ((uint2*)&g_outh[((size_t)(b0 + 1) * N_ + i) * DOUT_])[lane] = oB;
}

// ==== final: y = relu(adj @ out), warp per (row, graph-pair), 4-edge ========
__global__ __launch_bounds__(256) void final_kernel(float* __restrict__ y) {
    int lane = threadIdx.x & 31;
    int w = threadIdx.x >> 5;
    int rl = w >> 1, pr = w & 1;
    int i = blockIdx.x * 4 + rl;
    int deg = g_deg[i];
    int b0 = 2 * pr;

    const uint2* ouA = (const uint2*)g_outh + (size_t)b0 * N_ * 32;
    const uint2* ouB = ouA + (size_t)N_ * 32;
    float aA0 = 0.f, aA1 = 0.f, aA2 = 0.f, aA3 = 0.f;
    float aB0 = 0.f, aB1 = 0.f, aB2 = 0.f, aB3 = 0.f;

    int k = 0;
    for (; k + 4 <= deg; k += 4) {
        uint2 vA[4], vB[4];
#pragma unroll
        for (int u = 0; u < 4; u++) {
            size_t o = (size_t)g_cols[i * MAXDEG + k + u] * 32 + lane;
            vA[u] = ouA[o]; vB[u] = ouB[o];
        }
#pragma unroll
        for (int u = 0; u < 4; u++) {
            float2 f;
            f = __half22float2(*(__half2*)&vA[u].x); aA0 += f.x; aA1 += f.y;
            f = __half22float2(*(__half2*)&vA[u].y); aA2 += f.x; aA3 += f.y;
            f = __half22float2(*(__half2*)&vB[u].x); aB0 += f.x; aB1 += f.y;
            f = __half22float2(*(__half2*)&vB[u].y); aB2 += f.x; aB3 += f.y;
        }
    }
    for (; k < deg; k++) {
        size_t o0 = (size_t)g_cols[i * MAXDEG + k] * 32 + lane;
        uint2 vA0 = ouA[o0], vB0 = ouB[o0];
        float2 f;
        f = __half22float2(*(__half2*)&vA0.x); aA0 += f.x; aA1 += f.y;
        f = __half22float2(*(__half2*)&vA0.y); aA2 += f.x; aA3 += f.y;
        f = __half22float2(*(__half2*)&vB0.x); aB0 += f.x; aB1 += f.y;
        f = __half22float2(*(__half2*)&vB0.y); aB2 += f.x; aB3 += f.y;
    }
    float4 rA = make_float4(fmaxf(aA0, 0.f), fmaxf(aA1, 0.f),
                            fmaxf(aA2, 0.f), fmaxf(aA3, 0.f));
    float4 rB = make_float4(fmaxf(aB0, 0.f), fmaxf(aB1, 0.f),
                            fmaxf(aB2, 0.f), fmaxf(aB3, 0.f));
    ((float4*)&y[((size_t)b0 * N_ + i) * DOUT_])[lane] = rA;
    ((float4*)&y[((size_t)(b0 + 1) * N_ + i) * DOUT_])[lane] = rB;
}

// ---------------- launch ----------------
extern "C" void kernel_launch(void* const* d_in, const int* in_sizes, int n_in,
                              void* d_out, int out_size) {
    const float* x   = (const float*)d_in[0];  // (B, N, DIN)
    const float* adj = (const float*)d_in[1];  // (N, N)
    const float* wts = (const float*)d_in[2];  // (DIN, DOUT)
    const float* a   = (const float*)d_in[3];  // (2*DOUT, 1)
    float* y = (float*)d_out;

    static cudaStream_t s2;
    static cudaEvent_t evA, evC;
    static int inited = 0;
    if (!inited) {
        cudaFuncSetAttribute(gemm_hmma_kernel,
                             cudaFuncAttributeMaxDynamicSharedMemorySize, SMEM_TOTAL);
        cudaStreamCreateWithFlags(&s2, cudaStreamNonBlocking);
        cudaEventCreateWithFlags(&evA, cudaEventDisableTiming);
        cudaEventCreateWithFlags(&evC, cudaEventDisableTiming);
        inited = 1;
    }
    cudaStream_t s0 = 0;

    // fork: csr on s2 overlaps convW+GEMM on s0; join before attn
    cudaEventRecord(evA, s0);
    cudaStreamWaitEvent(s2, evA, 0);
    csr_build_kernel<<<N_ / 8, 256, 0, s2>>>(adj);
    cudaEventRecord(evC, s2);

    convw_kernel<<<DIN_ * DOUT_ / 1024, 256, 0, s0>>>(wts);
    gemm_hmma_kernel<<<(B_ * N_) / 64, 256, SMEM_TOTAL, s0>>>(x, a);
    cudaStreamWaitEvent(s0, evC, 0);

    attn_kernel<<<N_ / 4, 256, 0, s0>>>();
    final_kernel<<<N_ / 4, 256, 0, s0>>>(y);
}